// round 4
// baseline (speedup 1.0000x reference)
#include <cuda_runtime.h>
#include <cuda_bf16.h>
#include <math.h>

#define N_NODES 100000
#define N_EDGES 1600000
#define HID 128
#define OUT_D 128

// ---------------- device scratch (no allocations allowed) ----------------
// g_gath: per-node [t(128) | sl(128)]  (gathered by edges)
// g_epi : per-node [r(128) | sr(128)]  (used only in final epilogue)
// g_agg : per-node [aggA(128) | aggS(128)] (atomic accumulation targets)
__device__ float g_gath[(size_t)N_NODES * 256];
__device__ float g_epi [(size_t)N_NODES * 256];
__device__ float g_agg [(size_t)N_NODES * 256];
__device__ float g_Wf[128 * 512];   // fused weights: W_pre @ [Wi|Wr|Wsl|Wsr]
__device__ float g_bf[512];         // fused bias contribution of b_pre
__device__ float g_deg[N_NODES];
__device__ float g_cnt[N_NODES];
__device__ float g_dis[N_NODES];
__device__ int   g_is64;            // 1 if edge_index is int64 on device, 0 if int32

// ---------------- vectorized global reduction ----------------
__device__ __forceinline__ void red_add_v4(float* addr, float x, float y, float z, float w) {
    asm volatile("red.global.add.v4.f32 [%0], {%1, %2, %3, %4};"
                 :: "l"(addr), "f"(x), "f"(y), "f"(z), "f"(w) : "memory");
}

// ---------------- index fetch helper (dtype-robust) ----------------
__device__ __forceinline__ long long fetch_idx(const void* EI, int is64, size_t pos) {
    if (is64) return ((const long long*)EI)[pos];
    return (long long)((const int*)EI)[pos];
}

// ---------------- K-2: detect index dtype ----------------
// int64 indices (< 2^31) have zero high words; int32 data reinterpreted as
// int64 has random node ids in the "high word" slots -> nonzero.
__global__ void detect_kernel(const int* __restrict__ EI32) {
    __shared__ int bad;
    if (threadIdx.x == 0) bad = 0;
    __syncthreads();
    int hi = EI32[2 * threadIdx.x + 1];   // high word of int64 #threadIdx.x
    if (hi != 0) atomicOr(&bad, 1);
    __syncthreads();
    if (threadIdx.x == 0) g_is64 = (bad == 0) ? 1 : 0;
}

// ---------------- K-1: zero the accumulation scratch ----------------
__global__ void zero_kernel() {
    const size_t n4_agg = (size_t)N_NODES * 256 / 4;
    size_t i = (size_t)blockIdx.x * blockDim.x + threadIdx.x;
    size_t stride = (size_t)gridDim.x * blockDim.x;
    float4 z = make_float4(0.f, 0.f, 0.f, 0.f);
    for (size_t p = i; p < n4_agg; p += stride)
        ((float4*)g_agg)[p] = z;
    for (size_t p = i; p < N_NODES; p += stride) {
        g_deg[p] = 0.f;
        g_cnt[p] = 0.f;
    }
}

// ---------------- K0a: fuse weights  Wf = W_pre @ [Wi|Wr|Wsl|Wsr] ----------------
__global__ void fuse_w_kernel(const float* __restrict__ Wpre,
                              const float* __restrict__ w_ai,
                              const float* __restrict__ w_ar,
                              const float* __restrict__ w_sl,
                              const float* __restrict__ w_sr) {
    int c = blockIdx.x;      // 0..127 (input feature index = K of big GEMM)
    int j = threadIdx.x;     // 0..511
    __shared__ float wrow[128];
    if (j < 128) wrow[j] = Wpre[c * 128 + j];
    __syncthreads();
    const float* W2; int jj;
    if (j < 128)      { W2 = w_ai; jj = j;       }
    else if (j < 256) { W2 = w_ar; jj = j - 128; }
    else if (j < 384) { W2 = w_sl; jj = j - 256; }
    else              { W2 = w_sr; jj = j - 384; }
    float acc = 0.f;
    #pragma unroll 8
    for (int k = 0; k < 128; k++) acc += wrow[k] * W2[k * 128 + jj];
    g_Wf[c * 512 + j] = acc;
}

// ---------------- K0b: fused bias  bf = b_pre @ [Wi|Wr|Wsl|Wsr] ----------------
__global__ void fuse_b_kernel(const float* __restrict__ bpre,
                              const float* __restrict__ w_ai,
                              const float* __restrict__ w_ar,
                              const float* __restrict__ w_sl,
                              const float* __restrict__ w_sr) {
    int j = threadIdx.x;     // 0..511
    const float* W2; int jj;
    if (j < 128)      { W2 = w_ai; jj = j;       }
    else if (j < 256) { W2 = w_ar; jj = j - 128; }
    else if (j < 384) { W2 = w_sl; jj = j - 256; }
    else              { W2 = w_sr; jj = j - 384; }
    float acc = 0.f;
    for (int k = 0; k < 128; k++) acc += bpre[k] * W2[k * 128 + jj];
    g_bf[j] = acc;
}

// ---------------- K1: GEMM  Y[N,512] = X[N,128] @ Wf[128,512] + bf ----------------
// BM=128, BN=128, full K=128 resident in smem. 256 threads, 8x8 per thread.
// blockIdx.y selects the 128-wide weight quarter (0=t,1=r,2=sl,3=sr).
#define GEMM_APAD 4
__global__ void gemm_kernel(const float* __restrict__ X) {
    extern __shared__ float sm[];
    float* As = sm;                           // [128][128+GEMM_APAD]
    float* Bs = sm + 128 * (128 + GEMM_APAD); // [128][128]
    const int tid = threadIdx.x;
    const int m0 = blockIdx.x * 128;
    const int n0 = blockIdx.y * 128;

    #pragma unroll
    for (int i = 0; i < 16; i++) {
        int f = tid + i * 256;          // float4 index, 4096 total
        int r = f >> 5;                 // row 0..127
        int c4 = (f & 31) << 2;         // col 0,4,...,124
        float4 v = make_float4(0.f, 0.f, 0.f, 0.f);
        if (m0 + r < N_NODES)
            v = *(const float4*)&X[(size_t)(m0 + r) * 128 + c4];
        *(float4*)&As[r * (128 + GEMM_APAD) + c4] = v;
    }
    #pragma unroll
    for (int i = 0; i < 16; i++) {
        int f = tid + i * 256;
        int r = f >> 5;
        int c4 = (f & 31) << 2;
        float4 v = *(const float4*)&g_Wf[r * 512 + n0 + c4];
        *(float4*)&Bs[r * 128 + c4] = v;
    }
    __syncthreads();

    const int tx = tid & 15;   // n-tile: 8 cols at tx*8
    const int ty = tid >> 4;   // m-tile: 8 rows at ty*8
    float C[8][8];
    #pragma unroll
    for (int i = 0; i < 8; i++)
        #pragma unroll
        for (int j = 0; j < 8; j++) C[i][j] = 0.f;

    #pragma unroll 4
    for (int k = 0; k < 128; k++) {
        float a[8];
        #pragma unroll
        for (int i = 0; i < 8; i++) a[i] = As[(ty * 8 + i) * (128 + GEMM_APAD) + k];
        float4 b0 = *(float4*)&Bs[k * 128 + tx * 8];
        float4 b1 = *(float4*)&Bs[k * 128 + tx * 8 + 4];
        float b[8] = {b0.x, b0.y, b0.z, b0.w, b1.x, b1.y, b1.z, b1.w};
        #pragma unroll
        for (int i = 0; i < 8; i++)
            #pragma unroll
            for (int j = 0; j < 8; j++) C[i][j] += a[i] * b[j];
    }

    // epilogue: route quarter -> destination array/half
    const int wq = blockIdx.y;                       // 0=t,1=r,2=sl,3=sr
    float* dst = (wq == 0 || wq == 2) ? g_gath : g_epi;
    const int colbase = (wq >= 2) ? 128 : 0;
    float bias[8];
    #pragma unroll
    for (int j = 0; j < 8; j++) bias[j] = g_bf[n0 + tx * 8 + j];

    #pragma unroll
    for (int i = 0; i < 8; i++) {
        int m = m0 + ty * 8 + i;
        if (m >= N_NODES) continue;
        float* p = dst + (size_t)m * 256 + colbase + tx * 8;
        float4 v0 = make_float4(C[i][0] + bias[0], C[i][1] + bias[1],
                                C[i][2] + bias[2], C[i][3] + bias[3]);
        float4 v1 = make_float4(C[i][4] + bias[4], C[i][5] + bias[5],
                                C[i][6] + bias[6], C[i][7] + bias[7]);
        *(float4*)p = v0;
        *(float4*)(p + 4) = v1;
    }
}

// ---------------- K2: weighted in-degree + count ----------------
__global__ void deg_kernel(const void* __restrict__ EI,
                           const float* __restrict__ EW) {
    int e = blockIdx.x * blockDim.x + threadIdx.x;
    if (e >= N_EDGES) return;
    int is64 = g_is64;
    long long col = fetch_idx(EI, is64, (size_t)N_EDGES + e);
    if ((unsigned long long)col >= N_NODES) return;  // safety: never fault
    atomicAdd(&g_deg[col], EW[e]);
    atomicAdd(&g_cnt[col], 1.0f);
}

// ---------------- K3: dis = deg > 0 ? rsqrt(max(deg,1e-12)) : 0 ----------------
__global__ void dis_kernel() {
    int i = blockIdx.x * blockDim.x + threadIdx.x;
    if (i >= N_NODES) return;
    float d = g_deg[i];
    g_dis[i] = (d > 0.f) ? rsqrtf(fmaxf(d, 1e-12f)) : 0.f;
}

// ---------------- K4: fused edge scatter (ARMA + SAGE), 1 warp / edge ----------------
__global__ void scatter_kernel(const void* __restrict__ EI,
                               const float* __restrict__ EW) {
    int gid = blockIdx.x * blockDim.x + threadIdx.x;
    int e = gid >> 5;
    int lane = gid & 31;
    if (e >= N_EDGES) return;
    int is64 = g_is64;
    long long row = fetch_idx(EI, is64, (size_t)e);
    long long col = fetch_idx(EI, is64, (size_t)N_EDGES + e);
    if ((unsigned long long)row >= N_NODES) return;  // safety: never fault
    if ((unsigned long long)col >= N_NODES) return;
    float w = EW[e];
    float na = g_dis[row] * w * g_dis[col];

    const float4* src = (const float4*)(g_gath + (size_t)row * 256);
    float* dstA = g_agg + (size_t)col * 256 + lane * 4;   // ARMA half
    float4 tv = src[lane];        // t part  (cols 0..127)
    float4 sv = src[32 + lane];   // sl part (cols 128..255)
    red_add_v4(dstA,       na * tv.x, na * tv.y, na * tv.z, na * tv.w);
    red_add_v4(dstA + 128, w  * sv.x, w  * sv.y, w  * sv.z, w  * sv.w);
}

// ---------------- K5: final epilogue ----------------
__global__ void epilogue_kernel(const float* __restrict__ arma_b,
                                const float* __restrict__ sage_lb,
                                float* __restrict__ out) {
    int idx = blockIdx.x * blockDim.x + threadIdx.x;
    if (idx >= N_NODES * 256) return;
    int node = idx >> 8;
    int j = idx & 255;
    float agg = g_agg[idx];
    float ep  = g_epi[idx];
    float val;
    if (j < 128) {
        // relu -> leaky_relu -> elu collapses to relu (output >= 0)
        float v = agg + ep + arma_b[j];
        val = fmaxf(v, 0.f);
    } else {
        float cnt = g_cnt[node];
        float sage = agg / fmaxf(cnt, 1.f) + sage_lb[j - 128] + ep;
        // leaky_relu then elu: >=0 -> identity; <0 -> expm1(0.01*sage)
        val = (sage >= 0.f) ? sage : expm1f(0.01f * sage);
    }
    out[idx] = val;
}

// ---------------- host launcher ----------------
extern "C" void kernel_launch(void* const* d_in, const int* in_sizes, int n_in,
                              void* d_out, int out_size) {
    const float* x       = (const float*)d_in[0];
    const void*  ei      = d_in[1];                 // int32 or int64, detected on device
    const float* ew      = (const float*)d_in[2];
    const float* W_pre   = (const float*)d_in[3];
    const float* b_pre   = (const float*)d_in[4];
    const float* w_ai    = (const float*)d_in[5];
    const float* w_ar    = (const float*)d_in[6];
    const float* arma_b  = (const float*)d_in[7];
    const float* w_sl    = (const float*)d_in[8];
    const float* sage_lb = (const float*)d_in[9];
    const float* w_sr    = (const float*)d_in[10];
    float* out = (float*)d_out;

    // idempotent, called every time (no static guards allowed)
    cudaFuncSetAttribute(gemm_kernel, cudaFuncAttributeMaxDynamicSharedMemorySize,
                         (128 * (128 + GEMM_APAD) + 128 * 128) * sizeof(float));

    detect_kernel<<<1, 256>>>((const int*)ei);
    zero_kernel<<<2048, 256>>>();

    fuse_w_kernel<<<128, 512>>>(W_pre, w_ai, w_ar, w_sl, w_sr);
    fuse_b_kernel<<<1, 512>>>(b_pre, w_ai, w_ar, w_sl, w_sr);

    dim3 ggrid((N_NODES + 127) / 128, 4);
    size_t smem = (128 * (128 + GEMM_APAD) + 128 * 128) * sizeof(float);
    gemm_kernel<<<ggrid, 256, smem>>>(x);

    deg_kernel<<<(N_EDGES + 255) / 256, 256>>>(ei, ew);
    dis_kernel<<<(N_NODES + 255) / 256, 256>>>();

    long long tot = (long long)N_EDGES * 32;
    scatter_kernel<<<(unsigned)((tot + 255) / 256), 256>>>(ei, ew);

    epilogue_kernel<<<(N_NODES * 256 + 255) / 256, 256>>>(arma_b, sage_lb, out);
}

// round 5
// speedup vs baseline: 1.2509x; 1.2509x over previous
#include <cuda_runtime.h>
#include <cuda_bf16.h>
#include <math.h>

#define N_NODES 100000
#define N_EDGES 1600000
#define HID 128
#define OUT_D 128

// ---------------- device scratch (no allocations allowed) ----------------
// g_gath: per-node [t(128) | sl(128)]  (gathered by edges)
// g_epi : per-node [r(128) | sr(128)]  (used only in final epilogue)
// g_agg : per-node [aggA(128) | aggS(128)] (atomic accumulation targets)
__device__ float g_gath[(size_t)N_NODES * 256];
__device__ float g_epi [(size_t)N_NODES * 256];
__device__ float g_agg [(size_t)N_NODES * 256];
__device__ __nv_bfloat16 g_Wh[128 * 512];  // hi part of fused weights
__device__ __nv_bfloat16 g_Wl[128 * 512];  // lo part of fused weights
__device__ float g_bf[512];                // fused bias contribution of b_pre
__device__ float g_deg[N_NODES];
__device__ float g_cnt[N_NODES];
__device__ float g_dis[N_NODES];
__device__ int   g_is64;            // 1 if edge_index is int64 on device, 0 if int32

// ---------------- vectorized global reduction ----------------
__device__ __forceinline__ void red_add_v4(float* addr, float x, float y, float z, float w) {
    asm volatile("red.global.add.v4.f32 [%0], {%1, %2, %3, %4};"
                 :: "l"(addr), "f"(x), "f"(y), "f"(z), "f"(w) : "memory");
}

// ---------------- index fetch helper (dtype-robust) ----------------
__device__ __forceinline__ long long fetch_idx(const void* EI, int is64, size_t pos) {
    if (is64) return ((const long long*)EI)[pos];
    return (long long)((const int*)EI)[pos];
}

// ---------------- tensor-core helpers ----------------
__device__ __forceinline__ void ldsm_x4(unsigned& r0, unsigned& r1, unsigned& r2, unsigned& r3,
                                        unsigned addr) {
    asm volatile("ldmatrix.sync.aligned.m8n8.x4.shared.b16 {%0,%1,%2,%3}, [%4];"
                 : "=r"(r0), "=r"(r1), "=r"(r2), "=r"(r3) : "r"(addr));
}
__device__ __forceinline__ void ldsm_x4_t(unsigned& r0, unsigned& r1, unsigned& r2, unsigned& r3,
                                          unsigned addr) {
    asm volatile("ldmatrix.sync.aligned.m8n8.x4.trans.shared.b16 {%0,%1,%2,%3}, [%4];"
                 : "=r"(r0), "=r"(r1), "=r"(r2), "=r"(r3) : "r"(addr));
}
__device__ __forceinline__ void mma_bf16(float* c, const unsigned* a, unsigned b0, unsigned b1) {
    asm volatile("mma.sync.aligned.m16n8k16.row.col.f32.bf16.bf16.f32 "
                 "{%0,%1,%2,%3}, {%4,%5,%6,%7}, {%8,%9}, {%0,%1,%2,%3};"
                 : "+f"(c[0]), "+f"(c[1]), "+f"(c[2]), "+f"(c[3])
                 : "r"(a[0]), "r"(a[1]), "r"(a[2]), "r"(a[3]), "r"(b0), "r"(b1));
}

// ---------------- K-2: detect index dtype ----------------
__global__ void detect_kernel(const int* __restrict__ EI32) {
    __shared__ int bad;
    if (threadIdx.x == 0) bad = 0;
    __syncthreads();
    int hi = EI32[2 * threadIdx.x + 1];   // high word of int64 #threadIdx.x
    if (hi != 0) atomicOr(&bad, 1);
    __syncthreads();
    if (threadIdx.x == 0) g_is64 = (bad == 0) ? 1 : 0;
}

// ---------------- K-1: zero the accumulation scratch ----------------
__global__ void zero_kernel() {
    const size_t n4_agg = (size_t)N_NODES * 256 / 4;
    size_t i = (size_t)blockIdx.x * blockDim.x + threadIdx.x;
    size_t stride = (size_t)gridDim.x * blockDim.x;
    float4 z = make_float4(0.f, 0.f, 0.f, 0.f);
    for (size_t p = i; p < n4_agg; p += stride)
        ((float4*)g_agg)[p] = z;
    for (size_t p = i; p < N_NODES; p += stride) {
        g_deg[p] = 0.f;
        g_cnt[p] = 0.f;
    }
}

// ---------------- K0: fuse weights + bias, emit bf16 hi/lo split ----------------
// blocks 0..127: row c of Wf = W_pre[c,:] @ [Wi|Wr|Wsl|Wsr]  -> g_Wh/g_Wl
// block 128:     bias  bf = b_pre @ [Wi|Wr|Wsl|Wsr]          -> g_bf (fp32)
__global__ void fuse_w_kernel(const float* __restrict__ Wpre,
                              const float* __restrict__ bpre,
                              const float* __restrict__ w_ai,
                              const float* __restrict__ w_ar,
                              const float* __restrict__ w_sl,
                              const float* __restrict__ w_sr) {
    int c = blockIdx.x;      // 0..128
    int j = threadIdx.x;     // 0..511
    __shared__ float wrow[128];
    if (j < 128) wrow[j] = (c < 128) ? Wpre[c * 128 + j] : bpre[j];
    __syncthreads();
    const float* W2; int jj;
    if (j < 128)      { W2 = w_ai; jj = j;       }
    else if (j < 256) { W2 = w_ar; jj = j - 128; }
    else if (j < 384) { W2 = w_sl; jj = j - 256; }
    else              { W2 = w_sr; jj = j - 384; }
    float acc = 0.f;
    #pragma unroll 8
    for (int k = 0; k < 128; k++) acc += wrow[k] * W2[k * 128 + jj];
    if (c < 128) {
        __nv_bfloat16 hi = __float2bfloat16(acc);
        float lo = acc - __bfloat162float(hi);
        g_Wh[c * 512 + j] = hi;
        g_Wl[c * 512 + j] = __float2bfloat16(lo);
    } else {
        g_bf[j] = acc;
    }
}

// ---------------- K1: tensor-core GEMM  Y[N,512] = X @ Wf + bf ----------------
// Split-bf16 (3-term) with mma.sync m16n8k16, fp32 accumulate.
// BM=128, BN=128 (blockIdx.y = weight quarter), K=128 resident. 256 threads.
#define PITCH 136   // bf16 pitch: 272B rows -> ldmatrix conflict-free
#define TILE_B (128 * PITCH * 2)   // 34816 bytes per bf16 tile
__global__ void gemm_kernel(const float* __restrict__ X) {
    extern __shared__ __align__(16) char sm[];
    __nv_bfloat16* As_hi = (__nv_bfloat16*)sm;
    __nv_bfloat16* As_lo = (__nv_bfloat16*)(sm + TILE_B);
    __nv_bfloat16* Bs_hi = (__nv_bfloat16*)(sm + 2 * TILE_B);
    __nv_bfloat16* Bs_lo = (__nv_bfloat16*)(sm + 3 * TILE_B);

    const int tid = threadIdx.x;
    const int m0 = blockIdx.x * 128;
    const int n0 = blockIdx.y * 128;

    // ---- stage A (fp32 -> hi/lo bf16), 16 float4 per thread ----
    #pragma unroll
    for (int i = 0; i < 16; i++) {
        int f = tid + i * 256;            // 0..4095
        int r = f >> 5;                   // row 0..127
        int c4 = (f & 31) << 2;           // col 0,4,...,124
        float4 v = make_float4(0.f, 0.f, 0.f, 0.f);
        if (m0 + r < N_NODES)
            v = *(const float4*)&X[(size_t)(m0 + r) * 128 + c4];
        __nv_bfloat162 h01 = __floats2bfloat162_rn(v.x, v.y);
        __nv_bfloat162 h23 = __floats2bfloat162_rn(v.z, v.w);
        __nv_bfloat162 l01 = __floats2bfloat162_rn(v.x - __bfloat162float(h01.x),
                                                   v.y - __bfloat162float(h01.y));
        __nv_bfloat162 l23 = __floats2bfloat162_rn(v.z - __bfloat162float(h23.x),
                                                   v.w - __bfloat162float(h23.y));
        unsigned* ph = (unsigned*)&As_hi[r * PITCH + c4];
        unsigned* pl = (unsigned*)&As_lo[r * PITCH + c4];
        ph[0] = *(unsigned*)&h01; ph[1] = *(unsigned*)&h23;
        pl[0] = *(unsigned*)&l01; pl[1] = *(unsigned*)&l23;
    }
    // ---- stage B slice [128k][128n] from g_Wh/g_Wl ----
    #pragma unroll
    for (int i = 0; i < 16; i++) {
        int f = tid + i * 256;            // 0..4095 (uint2 = 4 bf16)
        int r = f >> 5;
        int c4 = (f & 31) << 2;
        uint2 vh = *(const uint2*)&g_Wh[r * 512 + n0 + c4];
        uint2 vl = *(const uint2*)&g_Wl[r * 512 + n0 + c4];
        *(uint2*)&Bs_hi[r * PITCH + c4] = vh;
        *(uint2*)&Bs_lo[r * PITCH + c4] = vl;
    }
    __syncthreads();

    const int lane = tid & 31;
    const int wid = tid >> 5;
    const int warp_m = wid & 3;   // 4 warps along m: 32 rows each
    const int warp_n = wid >> 2;  // 2 warps along n: 64 cols each

    float C[2][8][4];
    #pragma unroll
    for (int a = 0; a < 2; a++)
        #pragma unroll
        for (int b = 0; b < 8; b++)
            #pragma unroll
            for (int d = 0; d < 4; d++) C[a][b][d] = 0.f;

    const unsigned sa_hi = (unsigned)__cvta_generic_to_shared(As_hi);
    const unsigned sa_lo = (unsigned)__cvta_generic_to_shared(As_lo);
    const unsigned sb_hi = (unsigned)__cvta_generic_to_shared(Bs_hi);
    const unsigned sb_lo = (unsigned)__cvta_generic_to_shared(Bs_lo);
    const int lr = lane & 15;       // row-within-16
    const int lc = (lane >> 4) * 8; // col-half select

    #pragma unroll
    for (int ks = 0; ks < 8; ks++) {
        const int k0 = ks * 16;
        unsigned ah[2][4], al[2][4];
        #pragma unroll
        for (int mi = 0; mi < 2; mi++) {
            unsigned off = ((warp_m * 32 + mi * 16 + lr) * PITCH + k0 + lc) * 2;
            ldsm_x4(ah[mi][0], ah[mi][1], ah[mi][2], ah[mi][3], sa_hi + off);
            ldsm_x4(al[mi][0], al[mi][1], al[mi][2], al[mi][3], sa_lo + off);
        }
        unsigned bh[16], bl[16];
        #pragma unroll
        for (int nj = 0; nj < 4; nj++) {
            unsigned off = ((k0 + lr) * PITCH + warp_n * 64 + nj * 16 + lc) * 2;
            ldsm_x4_t(bh[nj*4], bh[nj*4+1], bh[nj*4+2], bh[nj*4+3], sb_hi + off);
            ldsm_x4_t(bl[nj*4], bl[nj*4+1], bl[nj*4+2], bl[nj*4+3], sb_lo + off);
        }
        #pragma unroll
        for (int mi = 0; mi < 2; mi++)
            #pragma unroll
            for (int nf = 0; nf < 8; nf++) {
                int bi = (nf >> 1) * 4 + (nf & 1) * 2;
                mma_bf16(C[mi][nf], ah[mi], bh[bi], bh[bi + 1]);  // hi*hi
                mma_bf16(C[mi][nf], ah[mi], bl[bi], bl[bi + 1]);  // hi*lo
                mma_bf16(C[mi][nf], al[mi], bh[bi], bh[bi + 1]);  // lo*hi
            }
    }

    // ---- epilogue: bias + route quarter -> destination array/half ----
    const int wq = blockIdx.y;                       // 0=t,1=r,2=sl,3=sr
    float* dst = (wq == 0 || wq == 2) ? g_gath : g_epi;
    const int colbase = (wq >= 2) ? 128 : 0;

    #pragma unroll
    for (int mi = 0; mi < 2; mi++) {
        #pragma unroll
        for (int nf = 0; nf < 8; nf++) {
            int ncol = warp_n * 64 + nf * 8 + (lane & 3) * 2;   // within 128
            float b0 = g_bf[n0 + ncol];
            float b1 = g_bf[n0 + ncol + 1];
            int r0 = m0 + warp_m * 32 + mi * 16 + (lane >> 2);
            if (r0 < N_NODES)
                *(float2*)&dst[(size_t)r0 * 256 + colbase + ncol] =
                    make_float2(C[mi][nf][0] + b0, C[mi][nf][1] + b1);
            int r1 = r0 + 8;
            if (r1 < N_NODES)
                *(float2*)&dst[(size_t)r1 * 256 + colbase + ncol] =
                    make_float2(C[mi][nf][2] + b0, C[mi][nf][3] + b1);
        }
    }
}

// ---------------- K2: weighted in-degree + count ----------------
__global__ void deg_kernel(const void* __restrict__ EI,
                           const float* __restrict__ EW) {
    int e = blockIdx.x * blockDim.x + threadIdx.x;
    if (e >= N_EDGES) return;
    int is64 = g_is64;
    long long col = fetch_idx(EI, is64, (size_t)N_EDGES + e);
    if ((unsigned long long)col >= N_NODES) return;  // safety: never fault
    atomicAdd(&g_deg[col], EW[e]);
    atomicAdd(&g_cnt[col], 1.0f);
}

// ---------------- K3: dis = deg > 0 ? rsqrt(max(deg,1e-12)) : 0 ----------------
__global__ void dis_kernel() {
    int i = blockIdx.x * blockDim.x + threadIdx.x;
    if (i >= N_NODES) return;
    float d = g_deg[i];
    g_dis[i] = (d > 0.f) ? rsqrtf(fmaxf(d, 1e-12f)) : 0.f;
}

// ---------------- K4: fused edge scatter (ARMA + SAGE), 1 warp / edge ----------------
__global__ void scatter_kernel(const void* __restrict__ EI,
                               const float* __restrict__ EW) {
    int gid = blockIdx.x * blockDim.x + threadIdx.x;
    int e = gid >> 5;
    int lane = gid & 31;
    if (e >= N_EDGES) return;
    int is64 = g_is64;
    long long row = fetch_idx(EI, is64, (size_t)e);
    long long col = fetch_idx(EI, is64, (size_t)N_EDGES + e);
    if ((unsigned long long)row >= N_NODES) return;  // safety: never fault
    if ((unsigned long long)col >= N_NODES) return;
    float w = EW[e];
    float na = g_dis[row] * w * g_dis[col];

    const float4* src = (const float4*)(g_gath + (size_t)row * 256);
    float* dstA = g_agg + (size_t)col * 256 + lane * 4;   // ARMA half
    float4 tv = src[lane];        // t part  (cols 0..127)
    float4 sv = src[32 + lane];   // sl part (cols 128..255)
    red_add_v4(dstA,       na * tv.x, na * tv.y, na * tv.z, na * tv.w);
    red_add_v4(dstA + 128, w  * sv.x, w  * sv.y, w  * sv.z, w  * sv.w);
}

// ---------------- K5: final epilogue ----------------
__global__ void epilogue_kernel(const float* __restrict__ arma_b,
                                const float* __restrict__ sage_lb,
                                float* __restrict__ out) {
    int idx = blockIdx.x * blockDim.x + threadIdx.x;
    if (idx >= N_NODES * 256) return;
    int node = idx >> 8;
    int j = idx & 255;
    float agg = g_agg[idx];
    float ep  = g_epi[idx];
    float val;
    if (j < 128) {
        // relu -> leaky_relu -> elu collapses to relu (output >= 0)
        float v = agg + ep + arma_b[j];
        val = fmaxf(v, 0.f);
    } else {
        float cnt = g_cnt[node];
        float sage = agg / fmaxf(cnt, 1.f) + sage_lb[j - 128] + ep;
        // leaky_relu then elu: >=0 -> identity; <0 -> expm1(0.01*sage)
        val = (sage >= 0.f) ? sage : expm1f(0.01f * sage);
    }
    out[idx] = val;
}

// ---------------- host launcher ----------------
extern "C" void kernel_launch(void* const* d_in, const int* in_sizes, int n_in,
                              void* d_out, int out_size) {
    const float* x       = (const float*)d_in[0];
    const void*  ei      = d_in[1];                 // int32 or int64, detected on device
    const float* ew      = (const float*)d_in[2];
    const float* W_pre   = (const float*)d_in[3];
    const float* b_pre   = (const float*)d_in[4];
    const float* w_ai    = (const float*)d_in[5];
    const float* w_ar    = (const float*)d_in[6];
    const float* arma_b  = (const float*)d_in[7];
    const float* w_sl    = (const float*)d_in[8];
    const float* sage_lb = (const float*)d_in[9];
    const float* w_sr    = (const float*)d_in[10];
    float* out = (float*)d_out;

    // idempotent, called every time (no static guards allowed)
    cudaFuncSetAttribute(gemm_kernel, cudaFuncAttributeMaxDynamicSharedMemorySize,
                         4 * TILE_B);

    // order chosen so ncu's (-s 5 -c 1) slot lands on gemm_kernel (launch #6)
    detect_kernel<<<1, 256>>>((const int*)ei);                         // 1
    zero_kernel<<<2048, 256>>>();                                      // 2
    deg_kernel<<<(N_EDGES + 255) / 256, 256>>>(ei, ew);                // 3
    dis_kernel<<<(N_NODES + 255) / 256, 256>>>();                      // 4
    fuse_w_kernel<<<129, 512>>>(W_pre, b_pre, w_ai, w_ar, w_sl, w_sr); // 5

    dim3 ggrid((N_NODES + 127) / 128, 4);
    gemm_kernel<<<ggrid, 256, 4 * TILE_B>>>(x);                        // 6

    long long tot = (long long)N_EDGES * 32;
    scatter_kernel<<<(unsigned)((tot + 255) / 256), 256>>>(ei, ew);    // 7

    epilogue_kernel<<<(N_NODES * 256 + 255) / 256, 256>>>(arma_b, sage_lb, out); // 8
}

// round 10
// speedup vs baseline: 1.7476x; 1.3971x over previous
#include <cuda_runtime.h>
#include <cuda_bf16.h>
#include <math.h>

#define N_NODES 100000
#define N_EDGES 1600000
#define HID 128
#define OUT_D 128
#define NCHUNK ((N_NODES + 127) / 128)   // 782 scan chunks

// ---------------- device scratch (no allocations allowed) ----------------
// g_gath: per-node [t(128) | sl(128)]  (gathered by edges)
// g_epi : per-node [r(128) | sr(128)]  (used only in final epilogue)
__device__ float g_gath[(size_t)N_NODES * 256];
__device__ float g_epi [(size_t)N_NODES * 256];
__device__ __nv_bfloat16 g_Wh[128 * 512];  // hi part of fused weights
__device__ __nv_bfloat16 g_Wl[128 * 512];  // lo part of fused weights
__device__ float g_bf[512];                // fused bias contribution of b_pre
__device__ float g_deg[N_NODES];           // weighted in-degree
__device__ int   g_cnti[N_NODES];          // integer in-degree
__device__ int   g_cursor[N_NODES];        // fill cursors
__device__ int   g_start[N_NODES];         // CSR start offsets
__device__ int   g_part[NCHUNK];           // scan partials
__device__ int   g_partoff[NCHUNK];        // scanned partials
__device__ float g_dis[N_NODES];
__device__ int   g_erow[N_EDGES];          // CSR: source node per slot
__device__ float g_ena[N_EDGES];           // CSR: dis[row]*w per slot
__device__ float g_ews[N_EDGES];           // CSR: w per slot
__device__ int   g_is64;                   // 1 if edge_index is int64 on device

// ---------------- index fetch helper (dtype-robust) ----------------
__device__ __forceinline__ long long fetch_idx(const void* EI, int is64, size_t pos) {
    if (is64) return ((const long long*)EI)[pos];
    return (long long)((const int*)EI)[pos];
}

// ---------------- tensor-core helpers ----------------
__device__ __forceinline__ void ldsm_x4(unsigned& r0, unsigned& r1, unsigned& r2, unsigned& r3,
                                        unsigned addr) {
    asm volatile("ldmatrix.sync.aligned.m8n8.x4.shared.b16 {%0,%1,%2,%3}, [%4];"
                 : "=r"(r0), "=r"(r1), "=r"(r2), "=r"(r3) : "r"(addr));
}
__device__ __forceinline__ void ldsm_x4_t(unsigned& r0, unsigned& r1, unsigned& r2, unsigned& r3,
                                          unsigned addr) {
    asm volatile("ldmatrix.sync.aligned.m8n8.x4.trans.shared.b16 {%0,%1,%2,%3}, [%4];"
                 : "=r"(r0), "=r"(r1), "=r"(r2), "=r"(r3) : "r"(addr));
}
__device__ __forceinline__ void mma_bf16(float* c, const unsigned* a, unsigned b0, unsigned b1) {
    asm volatile("mma.sync.aligned.m16n8k16.row.col.f32.bf16.bf16.f32 "
                 "{%0,%1,%2,%3}, {%4,%5,%6,%7}, {%8,%9}, {%0,%1,%2,%3};"
                 : "+f"(c[0]), "+f"(c[1]), "+f"(c[2]), "+f"(c[3])
                 : "r"(a[0]), "r"(a[1]), "r"(a[2]), "r"(a[3]), "r"(b0), "r"(b1));
}

// ---------------- detect index dtype ----------------
__global__ void detect_kernel(const int* __restrict__ EI32) {
    __shared__ int bad;
    if (threadIdx.x == 0) bad = 0;
    __syncthreads();
    int hi = EI32[2 * threadIdx.x + 1];   // high word of int64 #threadIdx.x
    if (hi != 0) atomicOr(&bad, 1);
    __syncthreads();
    if (threadIdx.x == 0) g_is64 = (bad == 0) ? 1 : 0;
}

// ---------------- zero small per-node scratch ----------------
__global__ void zero_kernel() {
    int i = blockIdx.x * blockDim.x + threadIdx.x;
    if (i >= N_NODES) return;
    g_deg[i] = 0.f;
    g_cnti[i] = 0;
    g_cursor[i] = 0;
}

// ---------------- histogram: weighted degree + count ----------------
__global__ void hist_kernel(const void* __restrict__ EI,
                            const float* __restrict__ EW) {
    int e = blockIdx.x * blockDim.x + threadIdx.x;
    if (e >= N_EDGES) return;
    long long col = fetch_idx(EI, g_is64, (size_t)N_EDGES + e);
    if ((unsigned long long)col >= N_NODES) return;  // safety
    atomicAdd(&g_deg[col], EW[e]);
    atomicAdd(&g_cnti[col], 1);
}

// ---------------- 2-level exclusive scan of g_cnti -> g_start ----------------
__global__ void scan1_kernel() {       // grid NCHUNK, block 128
    __shared__ int sd[128];
    int i = blockIdx.x * 128 + threadIdx.x;
    int v = (i < N_NODES) ? g_cnti[i] : 0;
    sd[threadIdx.x] = v;
    __syncthreads();
    #pragma unroll
    for (int off = 1; off < 128; off <<= 1) {
        int t = (threadIdx.x >= off) ? sd[threadIdx.x - off] : 0;
        __syncthreads();
        sd[threadIdx.x] += t;
        __syncthreads();
    }
    if (i < N_NODES) g_start[i] = sd[threadIdx.x] - v;   // exclusive
    if (threadIdx.x == 127) g_part[blockIdx.x] = sd[127];
}
__global__ void scan2_kernel() {       // 1 block, 1024 threads
    __shared__ int sd[1024];
    int v = (threadIdx.x < NCHUNK) ? g_part[threadIdx.x] : 0;
    sd[threadIdx.x] = v;
    __syncthreads();
    #pragma unroll
    for (int off = 1; off < 1024; off <<= 1) {
        int t = (threadIdx.x >= off) ? sd[threadIdx.x - off] : 0;
        __syncthreads();
        sd[threadIdx.x] += t;
        __syncthreads();
    }
    if (threadIdx.x < NCHUNK) g_partoff[threadIdx.x] = sd[threadIdx.x] - v;
}
__global__ void scan3_kernel() {       // grid NCHUNK, block 128
    int i = blockIdx.x * 128 + threadIdx.x;
    if (i < N_NODES) g_start[i] += g_partoff[blockIdx.x];
}

// ---------------- dis = deg > 0 ? rsqrt(max(deg,1e-12)) : 0 ----------------
__global__ void dis_kernel() {
    int i = blockIdx.x * blockDim.x + threadIdx.x;
    if (i >= N_NODES) return;
    float d = g_deg[i];
    g_dis[i] = (d > 0.f) ? rsqrtf(fmaxf(d, 1e-12f)) : 0.f;
}

// ---------------- fill CSR slots ----------------
__global__ void fill_kernel(const void* __restrict__ EI,
                            const float* __restrict__ EW) {
    int e = blockIdx.x * blockDim.x + threadIdx.x;
    if (e >= N_EDGES) return;
    int is64 = g_is64;
    long long row = fetch_idx(EI, is64, (size_t)e);
    long long col = fetch_idx(EI, is64, (size_t)N_EDGES + e);
    if ((unsigned long long)row >= N_NODES) return;  // safety
    if ((unsigned long long)col >= N_NODES) return;
    float w = EW[e];
    int pos = g_start[col] + atomicAdd(&g_cursor[col], 1);
    g_erow[pos] = (int)row;
    g_ena[pos]  = g_dis[row] * w;   // per-node dis[col] applied at aggregate
    g_ews[pos]  = w;
}

// ---------------- fuse weights + bias, emit bf16 hi/lo split ----------------
__global__ void fuse_w_kernel(const float* __restrict__ Wpre,
                              const float* __restrict__ bpre,
                              const float* __restrict__ w_ai,
                              const float* __restrict__ w_ar,
                              const float* __restrict__ w_sl,
                              const float* __restrict__ w_sr) {
    int c = blockIdx.x;      // 0..128
    int j = threadIdx.x;     // 0..511
    __shared__ float wrow[128];
    if (j < 128) wrow[j] = (c < 128) ? Wpre[c * 128 + j] : bpre[j];
    __syncthreads();
    const float* W2; int jj;
    if (j < 128)      { W2 = w_ai; jj = j;       }
    else if (j < 256) { W2 = w_ar; jj = j - 128; }
    else if (j < 384) { W2 = w_sl; jj = j - 256; }
    else              { W2 = w_sr; jj = j - 384; }
    float acc = 0.f;
    #pragma unroll 8
    for (int k = 0; k < 128; k++) acc += wrow[k] * W2[k * 128 + jj];
    if (c < 128) {
        __nv_bfloat16 hi = __float2bfloat16(acc);
        float lo = acc - __bfloat162float(hi);
        g_Wh[c * 512 + j] = hi;
        g_Wl[c * 512 + j] = __float2bfloat16(lo);
    } else {
        g_bf[j] = acc;
    }
}

// ---------------- tensor-core GEMM  Y[N,512] = X @ Wf + bf ----------------
#define PITCH 136   // bf16 pitch: 272B rows -> ldmatrix conflict-free
#define TILE_B (128 * PITCH * 2)   // 34816 bytes per bf16 tile
__global__ void gemm_kernel(const float* __restrict__ X) {
    extern __shared__ __align__(16) char sm[];
    __nv_bfloat16* As_hi = (__nv_bfloat16*)sm;
    __nv_bfloat16* As_lo = (__nv_bfloat16*)(sm + TILE_B);
    __nv_bfloat16* Bs_hi = (__nv_bfloat16*)(sm + 2 * TILE_B);
    __nv_bfloat16* Bs_lo = (__nv_bfloat16*)(sm + 3 * TILE_B);

    const int tid = threadIdx.x;
    const int m0 = blockIdx.x * 128;
    const int n0 = blockIdx.y * 128;

    #pragma unroll
    for (int i = 0; i < 16; i++) {
        int f = tid + i * 256;            // 0..4095
        int r = f >> 5;                   // row 0..127
        int c4 = (f & 31) << 2;           // col 0,4,...,124
        float4 v = make_float4(0.f, 0.f, 0.f, 0.f);
        if (m0 + r < N_NODES)
            v = *(const float4*)&X[(size_t)(m0 + r) * 128 + c4];
        __nv_bfloat162 h01 = __floats2bfloat162_rn(v.x, v.y);
        __nv_bfloat162 h23 = __floats2bfloat162_rn(v.z, v.w);
        __nv_bfloat162 l01 = __floats2bfloat162_rn(v.x - __bfloat162float(h01.x),
                                                   v.y - __bfloat162float(h01.y));
        __nv_bfloat162 l23 = __floats2bfloat162_rn(v.z - __bfloat162float(h23.x),
                                                   v.w - __bfloat162float(h23.y));
        unsigned* ph = (unsigned*)&As_hi[r * PITCH + c4];
        unsigned* pl = (unsigned*)&As_lo[r * PITCH + c4];
        ph[0] = *(unsigned*)&h01; ph[1] = *(unsigned*)&h23;
        pl[0] = *(unsigned*)&l01; pl[1] = *(unsigned*)&l23;
    }
    #pragma unroll
    for (int i = 0; i < 16; i++) {
        int f = tid + i * 256;            // 0..4095 (uint2 = 4 bf16)
        int r = f >> 5;
        int c4 = (f & 31) << 2;
        uint2 vh = *(const uint2*)&g_Wh[r * 512 + n0 + c4];
        uint2 vl = *(const uint2*)&g_Wl[r * 512 + n0 + c4];
        *(uint2*)&Bs_hi[r * PITCH + c4] = vh;
        *(uint2*)&Bs_lo[r * PITCH + c4] = vl;
    }
    __syncthreads();

    const int lane = tid & 31;
    const int wid = tid >> 5;
    const int warp_m = wid & 3;   // 4 warps along m: 32 rows each
    const int warp_n = wid >> 2;  // 2 warps along n: 64 cols each

    float C[2][8][4];
    #pragma unroll
    for (int a = 0; a < 2; a++)
        #pragma unroll
        for (int b = 0; b < 8; b++)
            #pragma unroll
            for (int d = 0; d < 4; d++) C[a][b][d] = 0.f;

    const unsigned sa_hi = (unsigned)__cvta_generic_to_shared(As_hi);
    const unsigned sa_lo = (unsigned)__cvta_generic_to_shared(As_lo);
    const unsigned sb_hi = (unsigned)__cvta_generic_to_shared(Bs_hi);
    const unsigned sb_lo = (unsigned)__cvta_generic_to_shared(Bs_lo);
    const int lr = lane & 15;       // row-within-16
    const int lc = (lane >> 4) * 8; // col-half select

    #pragma unroll
    for (int ks = 0; ks < 8; ks++) {
        const int k0 = ks * 16;
        unsigned ah[2][4], al[2][4];
        #pragma unroll
        for (int mi = 0; mi < 2; mi++) {
            unsigned off = ((warp_m * 32 + mi * 16 + lr) * PITCH + k0 + lc) * 2;
            ldsm_x4(ah[mi][0], ah[mi][1], ah[mi][2], ah[mi][3], sa_hi + off);
            ldsm_x4(al[mi][0], al[mi][1], al[mi][2], al[mi][3], sa_lo + off);
        }
        unsigned bh[16], bl[16];
        #pragma unroll
        for (int nj = 0; nj < 4; nj++) {
            unsigned off = ((k0 + lr) * PITCH + warp_n * 64 + nj * 16 + lc) * 2;
            ldsm_x4_t(bh[nj*4], bh[nj*4+1], bh[nj*4+2], bh[nj*4+3], sb_hi + off);
            ldsm_x4_t(bl[nj*4], bl[nj*4+1], bl[nj*4+2], bl[nj*4+3], sb_lo + off);
        }
        #pragma unroll
        for (int mi = 0; mi < 2; mi++)
            #pragma unroll
            for (int nf = 0; nf < 8; nf++) {
                int bi = (nf >> 1) * 4 + (nf & 1) * 2;
                mma_bf16(C[mi][nf], ah[mi], bh[bi], bh[bi + 1]);  // hi*hi
                mma_bf16(C[mi][nf], ah[mi], bl[bi], bl[bi + 1]);  // hi*lo
                mma_bf16(C[mi][nf], al[mi], bh[bi], bh[bi + 1]);  // lo*hi
            }
    }

    const int wq = blockIdx.y;                       // 0=t,1=r,2=sl,3=sr
    float* dst = (wq == 0 || wq == 2) ? g_gath : g_epi;
    const int colbase = (wq >= 2) ? 128 : 0;

    #pragma unroll
    for (int mi = 0; mi < 2; mi++) {
        #pragma unroll
        for (int nf = 0; nf < 8; nf++) {
            int ncol = warp_n * 64 + nf * 8 + (lane & 3) * 2;   // within 128
            float b0 = g_bf[n0 + ncol];
            float b1 = g_bf[n0 + ncol + 1];
            int r0 = m0 + warp_m * 32 + mi * 16 + (lane >> 2);
            if (r0 < N_NODES)
                *(float2*)&dst[(size_t)r0 * 256 + colbase + ncol] =
                    make_float2(C[mi][nf][0] + b0, C[mi][nf][1] + b1);
            int r1 = r0 + 8;
            if (r1 < N_NODES)
                *(float2*)&dst[(size_t)r1 * 256 + colbase + ncol] =
                    make_float2(C[mi][nf][2] + b0, C[mi][nf][3] + b1);
        }
    }
}

// ---------------- fused CSR aggregate + epilogue (no atomics) ----------------
// One 128-thread block per destination node. Register accumulation, each
// output element written exactly once.
__global__ void __launch_bounds__(128) agg_kernel(const float* __restrict__ arma_b,
                                                  const float* __restrict__ sage_lb,
                                                  float* __restrict__ out) {
    const int node = blockIdx.x;
    const int tid = threadIdx.x;   // 0..127
    const int s = g_start[node];
    const int cnt = g_cnti[node];
    const int e_end = s + cnt;

    float accA = 0.f, accS = 0.f;
    int e = s;
    // unroll-by-2 for MLP
    for (; e + 2 <= e_end; e += 2) {
        int   r0 = g_erow[e],     r1 = g_erow[e + 1];
        float m0 = g_ena[e],      m1 = g_ena[e + 1];
        float w0 = g_ews[e],      w1 = g_ews[e + 1];
        const float* s0 = g_gath + (size_t)r0 * 256;
        const float* s1 = g_gath + (size_t)r1 * 256;
        float t0 = s0[tid], v0 = s0[128 + tid];
        float t1 = s1[tid], v1 = s1[128 + tid];
        accA += m0 * t0 + m1 * t1;
        accS += w0 * v0 + w1 * v1;
    }
    if (e < e_end) {
        int   r0 = g_erow[e];
        float m0 = g_ena[e];
        float w0 = g_ews[e];
        const float* s0 = g_gath + (size_t)r0 * 256;
        accA += m0 * s0[tid];
        accS += w0 * s0[128 + tid];
    }
    accA *= g_dis[node];

    const float* ep = g_epi + (size_t)node * 256;
    // ARMA: relu (leaky_relu+elu collapse on non-negative input)
    float v = accA + ep[tid] + arma_b[tid];
    out[(size_t)node * 256 + tid] = fmaxf(v, 0.f);
    // SAGE: mean + lin + root, then leaky_relu -> elu
    float sage = accS / fmaxf((float)cnt, 1.f) + sage_lb[tid] + ep[128 + tid];
    out[(size_t)node * 256 + 128 + tid] = (sage >= 0.f) ? sage : expm1f(0.01f * sage);
}

// ---------------- host launcher ----------------
extern "C" void kernel_launch(void* const* d_in, const int* in_sizes, int n_in,
                              void* d_out, int out_size) {
    const float* x       = (const float*)d_in[0];
    const void*  ei      = d_in[1];                 // int32 or int64, detected on device
    const float* ew      = (const float*)d_in[2];
    const float* W_pre   = (const float*)d_in[3];
    const float* b_pre   = (const float*)d_in[4];
    const float* w_ai    = (const float*)d_in[5];
    const float* w_ar    = (const float*)d_in[6];
    const float* arma_b  = (const float*)d_in[7];
    const float* w_sl    = (const float*)d_in[8];
    const float* sage_lb = (const float*)d_in[9];
    const float* w_sr    = (const float*)d_in[10];
    float* out = (float*)d_out;

    cudaFuncSetAttribute(gemm_kernel, cudaFuncAttributeMaxDynamicSharedMemorySize,
                         4 * TILE_B);

    detect_kernel<<<1, 256>>>((const int*)ei);
    zero_kernel<<<(N_NODES + 255) / 256, 256>>>();
    hist_kernel<<<(N_EDGES + 255) / 256, 256>>>(ei, ew);
    scan1_kernel<<<NCHUNK, 128>>>();
    scan2_kernel<<<1, 1024>>>();
    scan3_kernel<<<NCHUNK, 128>>>();
    dis_kernel<<<(N_NODES + 255) / 256, 256>>>();
    fill_kernel<<<(N_EDGES + 255) / 256, 256>>>(ei, ew);

    fuse_w_kernel<<<129, 512>>>(W_pre, b_pre, w_ai, w_ar, w_sl, w_sr);
    dim3 ggrid((N_NODES + 127) / 128, 4);
    gemm_kernel<<<ggrid, 256, 4 * TILE_B>>>(x);

    agg_kernel<<<N_NODES, 128>>>(arma_b, sage_lb, out);
}

// round 11
// speedup vs baseline: 1.7967x; 1.0281x over previous
#include <cuda_runtime.h>
#include <cuda_bf16.h>
#include <math.h>

#define N_NODES 100000
#define N_EDGES 1600000
#define HID 128
#define OUT_D 128
#define NCHUNK ((N_NODES + 127) / 128)   // 782 scan chunks

// ---------------- device scratch (no allocations allowed) ----------------
__device__ float g_gath[(size_t)N_NODES * 256];   // per-node [t(128)|sl(128)]
__device__ float g_epi [(size_t)N_NODES * 256];   // per-node [r(128)|sr(128)]
__device__ __nv_bfloat16 g_Wh[128 * 512];  // hi part of fused weights
__device__ __nv_bfloat16 g_Wl[128 * 512];  // lo part of fused weights
__device__ float g_bf[512];                // fused bias contribution of b_pre
__device__ float g_deg[N_NODES];           // weighted in-degree
__device__ int   g_cnti[N_NODES];          // integer in-degree
__device__ int   g_cursor[N_NODES];        // fill cursors
__device__ int   g_start[N_NODES];         // CSR start offsets
__device__ int   g_part[NCHUNK];           // scan partials
__device__ int   g_partoff[NCHUNK];        // scanned partials
__device__ float g_dis[N_NODES];
__device__ int   g_erow[N_EDGES];          // CSR: source node per slot
__device__ float g_ena[N_EDGES];           // CSR: dis[row]*w per slot
__device__ float g_ews[N_EDGES];           // CSR: w per slot
__device__ int   g_is64;                   // 1 if edge_index is int64 on device

// ---------------- index fetch helper (dtype-robust) ----------------
__device__ __forceinline__ long long fetch_idx(const void* EI, int is64, size_t pos) {
    if (is64) return ((const long long*)EI)[pos];
    return (long long)((const int*)EI)[pos];
}

// ---------------- tensor-core helpers ----------------
__device__ __forceinline__ void ldsm_x4(unsigned& r0, unsigned& r1, unsigned& r2, unsigned& r3,
                                        unsigned addr) {
    asm volatile("ldmatrix.sync.aligned.m8n8.x4.shared.b16 {%0,%1,%2,%3}, [%4];"
                 : "=r"(r0), "=r"(r1), "=r"(r2), "=r"(r3) : "r"(addr));
}
__device__ __forceinline__ void ldsm_x4_t(unsigned& r0, unsigned& r1, unsigned& r2, unsigned& r3,
                                          unsigned addr) {
    asm volatile("ldmatrix.sync.aligned.m8n8.x4.trans.shared.b16 {%0,%1,%2,%3}, [%4];"
                 : "=r"(r0), "=r"(r1), "=r"(r2), "=r"(r3) : "r"(addr));
}
__device__ __forceinline__ void mma_bf16(float* c, const unsigned* a, unsigned b0, unsigned b1) {
    asm volatile("mma.sync.aligned.m16n8k16.row.col.f32.bf16.bf16.f32 "
                 "{%0,%1,%2,%3}, {%4,%5,%6,%7}, {%8,%9}, {%0,%1,%2,%3};"
                 : "+f"(c[0]), "+f"(c[1]), "+f"(c[2]), "+f"(c[3])
                 : "r"(a[0]), "r"(a[1]), "r"(a[2]), "r"(a[3]), "r"(b0), "r"(b1));
}

// ---------------- detect index dtype ----------------
__global__ void detect_kernel(const int* __restrict__ EI32) {
    __shared__ int bad;
    if (threadIdx.x == 0) bad = 0;
    __syncthreads();
    int hi = EI32[2 * threadIdx.x + 1];   // high word of int64 #threadIdx.x
    if (hi != 0) atomicOr(&bad, 1);
    __syncthreads();
    if (threadIdx.x == 0) g_is64 = (bad == 0) ? 1 : 0;
}

// ---------------- zero small per-node scratch ----------------
__global__ void zero_kernel() {
    int i = blockIdx.x * blockDim.x + threadIdx.x;
    if (i >= N_NODES) return;
    g_deg[i] = 0.f;
    g_cnti[i] = 0;
    g_cursor[i] = 0;
}

// ---------------- histogram: weighted degree + count ----------------
__global__ void hist_kernel(const void* __restrict__ EI,
                            const float* __restrict__ EW) {
    int e = blockIdx.x * blockDim.x + threadIdx.x;
    if (e >= N_EDGES) return;
    long long col = fetch_idx(EI, g_is64, (size_t)N_EDGES + e);
    if ((unsigned long long)col >= N_NODES) return;  // safety
    atomicAdd(&g_deg[col], EW[e]);
    atomicAdd(&g_cnti[col], 1);
}

// ---------------- 2-level exclusive scan of g_cnti -> g_start ----------------
__global__ void scan1_kernel() {       // grid NCHUNK, block 128
    __shared__ int sd[128];
    int i = blockIdx.x * 128 + threadIdx.x;
    int v = (i < N_NODES) ? g_cnti[i] : 0;
    sd[threadIdx.x] = v;
    __syncthreads();
    #pragma unroll
    for (int off = 1; off < 128; off <<= 1) {
        int t = (threadIdx.x >= off) ? sd[threadIdx.x - off] : 0;
        __syncthreads();
        sd[threadIdx.x] += t;
        __syncthreads();
    }
    if (i < N_NODES) g_start[i] = sd[threadIdx.x] - v;   // exclusive
    if (threadIdx.x == 127) g_part[blockIdx.x] = sd[127];
}
__global__ void scan2_kernel() {       // 1 block, 1024 threads
    __shared__ int sd[1024];
    int v = (threadIdx.x < NCHUNK) ? g_part[threadIdx.x] : 0;
    sd[threadIdx.x] = v;
    __syncthreads();
    #pragma unroll
    for (int off = 1; off < 1024; off <<= 1) {
        int t = (threadIdx.x >= off) ? sd[threadIdx.x - off] : 0;
        __syncthreads();
        sd[threadIdx.x] += t;
        __syncthreads();
    }
    if (threadIdx.x < NCHUNK) g_partoff[threadIdx.x] = sd[threadIdx.x] - v;
}
__global__ void scan3_kernel() {       // grid NCHUNK, block 128
    int i = blockIdx.x * 128 + threadIdx.x;
    if (i < N_NODES) g_start[i] += g_partoff[blockIdx.x];
}

// ---------------- dis = deg > 0 ? rsqrt(max(deg,1e-12)) : 0 ----------------
__global__ void dis_kernel() {
    int i = blockIdx.x * blockDim.x + threadIdx.x;
    if (i >= N_NODES) return;
    float d = g_deg[i];
    g_dis[i] = (d > 0.f) ? rsqrtf(fmaxf(d, 1e-12f)) : 0.f;
}

// ---------------- fill CSR slots ----------------
__global__ void fill_kernel(const void* __restrict__ EI,
                            const float* __restrict__ EW) {
    int e = blockIdx.x * blockDim.x + threadIdx.x;
    if (e >= N_EDGES) return;
    int is64 = g_is64;
    long long row = fetch_idx(EI, is64, (size_t)e);
    long long col = fetch_idx(EI, is64, (size_t)N_EDGES + e);
    if ((unsigned long long)row >= N_NODES) return;  // safety
    if ((unsigned long long)col >= N_NODES) return;
    float w = EW[e];
    int pos = g_start[col] + atomicAdd(&g_cursor[col], 1);
    g_erow[pos] = (int)row;
    g_ena[pos]  = g_dis[row] * w;   // per-node dis[col] applied at aggregate
    g_ews[pos]  = w;
}

// ---------------- fuse weights + bias, emit bf16 hi/lo split ----------------
__global__ void fuse_w_kernel(const float* __restrict__ Wpre,
                              const float* __restrict__ bpre,
                              const float* __restrict__ w_ai,
                              const float* __restrict__ w_ar,
                              const float* __restrict__ w_sl,
                              const float* __restrict__ w_sr) {
    int c = blockIdx.x;      // 0..128
    int j = threadIdx.x;     // 0..511
    __shared__ float wrow[128];
    if (j < 128) wrow[j] = (c < 128) ? Wpre[c * 128 + j] : bpre[j];
    __syncthreads();
    const float* W2; int jj;
    if (j < 128)      { W2 = w_ai; jj = j;       }
    else if (j < 256) { W2 = w_ar; jj = j - 128; }
    else if (j < 384) { W2 = w_sl; jj = j - 256; }
    else              { W2 = w_sr; jj = j - 384; }
    float acc = 0.f;
    #pragma unroll 8
    for (int k = 0; k < 128; k++) acc += wrow[k] * W2[k * 128 + jj];
    if (c < 128) {
        __nv_bfloat16 hi = __float2bfloat16(acc);
        float lo = acc - __bfloat162float(hi);
        g_Wh[c * 512 + j] = hi;
        g_Wl[c * 512 + j] = __float2bfloat16(lo);
    } else {
        g_bf[j] = acc;
    }
}

// ---------------- tensor-core GEMM  Y[N,512] = X @ Wf + bf ----------------
// BM=128, BN=64 (blockIdx.y = 64-col slice of 512), K=128 resident.
// smem = 106.5 KB -> 2 CTAs/SM for latency hiding. 256 threads.
#define PITCH 136    // A bf16 pitch (272B rows)
#define BPITCH 72    // B bf16 pitch (144B rows)
#define ATILE_B (128 * PITCH * 2)    // 34816 B
#define BTILE_B (128 * BPITCH * 2)   // 18432 B
#define GEMM_SMEM (2 * ATILE_B + 2 * BTILE_B)   // 106496 B
__global__ void __launch_bounds__(256, 2) gemm_kernel(const float* __restrict__ X) {
    extern __shared__ __align__(16) char sm[];
    __nv_bfloat16* As_hi = (__nv_bfloat16*)sm;
    __nv_bfloat16* As_lo = (__nv_bfloat16*)(sm + ATILE_B);
    __nv_bfloat16* Bs_hi = (__nv_bfloat16*)(sm + 2 * ATILE_B);
    __nv_bfloat16* Bs_lo = (__nv_bfloat16*)(sm + 2 * ATILE_B + BTILE_B);

    const int tid = threadIdx.x;
    const int m0 = blockIdx.x * 128;
    const int n0 = blockIdx.y * 64;       // within 512

    // ---- stage A (fp32 -> hi/lo bf16), 16 float4 per thread ----
    #pragma unroll
    for (int i = 0; i < 16; i++) {
        int f = tid + i * 256;            // 0..4095
        int r = f >> 5;                   // row 0..127
        int c4 = (f & 31) << 2;           // col 0,4,...,124
        float4 v = make_float4(0.f, 0.f, 0.f, 0.f);
        if (m0 + r < N_NODES)
            v = *(const float4*)&X[(size_t)(m0 + r) * 128 + c4];
        __nv_bfloat162 h01 = __floats2bfloat162_rn(v.x, v.y);
        __nv_bfloat162 h23 = __floats2bfloat162_rn(v.z, v.w);
        __nv_bfloat162 l01 = __floats2bfloat162_rn(v.x - __bfloat162float(h01.x),
                                                   v.y - __bfloat162float(h01.y));
        __nv_bfloat162 l23 = __floats2bfloat162_rn(v.z - __bfloat162float(h23.x),
                                                   v.w - __bfloat162float(h23.y));
        unsigned* ph = (unsigned*)&As_hi[r * PITCH + c4];
        unsigned* pl = (unsigned*)&As_lo[r * PITCH + c4];
        ph[0] = *(unsigned*)&h01; ph[1] = *(unsigned*)&h23;
        pl[0] = *(unsigned*)&l01; pl[1] = *(unsigned*)&l23;
    }
    // ---- stage B slice [128k][64n]: 8 uint2 per thread per tile ----
    #pragma unroll
    for (int i = 0; i < 8; i++) {
        int f = tid + i * 256;            // 0..2047 (uint2 = 4 bf16)
        int r = f >> 4;                   // row 0..127 (16 uint2 per row)
        int c4 = (f & 15) << 2;           // col 0,4,...,60
        uint2 vh = *(const uint2*)&g_Wh[r * 512 + n0 + c4];
        uint2 vl = *(const uint2*)&g_Wl[r * 512 + n0 + c4];
        *(uint2*)&Bs_hi[r * BPITCH + c4] = vh;
        *(uint2*)&Bs_lo[r * BPITCH + c4] = vl;
    }
    __syncthreads();

    const int lane = tid & 31;
    const int wid = tid >> 5;
    const int warp_m = wid & 3;   // 4 warps along m: 32 rows each
    const int warp_n = wid >> 2;  // 2 warps along n: 32 cols each

    float C[2][4][4];
    #pragma unroll
    for (int a = 0; a < 2; a++)
        #pragma unroll
        for (int b = 0; b < 4; b++)
            #pragma unroll
            for (int d = 0; d < 4; d++) C[a][b][d] = 0.f;

    const unsigned sa_hi = (unsigned)__cvta_generic_to_shared(As_hi);
    const unsigned sa_lo = (unsigned)__cvta_generic_to_shared(As_lo);
    const unsigned sb_hi = (unsigned)__cvta_generic_to_shared(Bs_hi);
    const unsigned sb_lo = (unsigned)__cvta_generic_to_shared(Bs_lo);
    const int lr = lane & 15;       // row-within-16
    const int lc = (lane >> 4) * 8; // col-half select

    #pragma unroll
    for (int ks = 0; ks < 8; ks++) {
        const int k0 = ks * 16;
        unsigned ah[2][4], al[2][4];
        #pragma unroll
        for (int mi = 0; mi < 2; mi++) {
            unsigned off = ((warp_m * 32 + mi * 16 + lr) * PITCH + k0 + lc) * 2;
            ldsm_x4(ah[mi][0], ah[mi][1], ah[mi][2], ah[mi][3], sa_hi + off);
            ldsm_x4(al[mi][0], al[mi][1], al[mi][2], al[mi][3], sa_lo + off);
        }
        unsigned bh[8], bl[8];
        #pragma unroll
        for (int nj = 0; nj < 2; nj++) {
            unsigned off = ((k0 + lr) * BPITCH + warp_n * 32 + nj * 16 + lc) * 2;
            ldsm_x4_t(bh[nj*4], bh[nj*4+1], bh[nj*4+2], bh[nj*4+3], sb_hi + off);
            ldsm_x4_t(bl[nj*4], bl[nj*4+1], bl[nj*4+2], bl[nj*4+3], sb_lo + off);
        }
        #pragma unroll
        for (int mi = 0; mi < 2; mi++)
            #pragma unroll
            for (int nf = 0; nf < 4; nf++) {
                int bi = (nf >> 1) * 4 + (nf & 1) * 2;
                mma_bf16(C[mi][nf], ah[mi], bh[bi], bh[bi + 1]);  // hi*hi
                mma_bf16(C[mi][nf], ah[mi], bl[bi], bl[bi + 1]);  // hi*lo
                mma_bf16(C[mi][nf], al[mi], bh[bi], bh[bi + 1]);  // lo*hi
            }
    }

    // ---- epilogue: bias + route quarter -> destination array/half ----
    const int wq = blockIdx.y >> 1;                  // 0=t,1=r,2=sl,3=sr
    const int half = blockIdx.y & 1;                 // which 64-col half of quarter
    float* dst = (wq == 0 || wq == 2) ? g_gath : g_epi;
    const int colbase = ((wq >= 2) ? 128 : 0) + half * 64;
    const bool to_epi = (wq == 1 || wq == 3);

    #pragma unroll
    for (int mi = 0; mi < 2; mi++) {
        #pragma unroll
        for (int nf = 0; nf < 4; nf++) {
            int ncol = warp_n * 32 + nf * 8 + (lane & 3) * 2;   // within 64
            float b0 = g_bf[n0 + ncol];
            float b1 = g_bf[n0 + ncol + 1];
            int r0 = m0 + warp_m * 32 + mi * 16 + (lane >> 2);
            if (r0 < N_NODES) {
                float2 v = make_float2(C[mi][nf][0] + b0, C[mi][nf][1] + b1);
                float2* p = (float2*)&dst[(size_t)r0 * 256 + colbase + ncol];
                if (to_epi) __stcs(p, v); else *p = v;   // epi: evict-first
            }
            int r1 = r0 + 8;
            if (r1 < N_NODES) {
                float2 v = make_float2(C[mi][nf][2] + b0, C[mi][nf][3] + b1);
                float2* p = (float2*)&dst[(size_t)r1 * 256 + colbase + ncol];
                if (to_epi) __stcs(p, v); else *p = v;
            }
        }
    }
}

// ---------------- fused CSR aggregate + epilogue (no atomics) ----------------
// One 128-thread block per destination node. Streaming data uses evict-first
// hints so g_gath stays L2-resident for the random gathers.
__global__ void __launch_bounds__(128) agg_kernel(const float* __restrict__ arma_b,
                                                  const float* __restrict__ sage_lb,
                                                  float* __restrict__ out) {
    const int node = blockIdx.x;
    const int tid = threadIdx.x;   // 0..127
    const int s = g_start[node];
    const int cnt = g_cnti[node];
    const int e_end = s + cnt;

    float accA = 0.f, accS = 0.f;
    int e = s;
    for (; e + 2 <= e_end; e += 2) {
        int   r0 = __ldcs(&g_erow[e]),  r1 = __ldcs(&g_erow[e + 1]);
        float m0 = __ldcs(&g_ena[e]),   m1 = __ldcs(&g_ena[e + 1]);
        float w0 = __ldcs(&g_ews[e]),   w1 = __ldcs(&g_ews[e + 1]);
        const float* s0 = g_gath + (size_t)r0 * 256;
        const float* s1 = g_gath + (size_t)r1 * 256;
        float t0 = s0[tid], v0 = s0[128 + tid];
        float t1 = s1[tid], v1 = s1[128 + tid];
        accA += m0 * t0 + m1 * t1;
        accS += w0 * v0 + w1 * v1;
    }
    if (e < e_end) {
        int   r0 = __ldcs(&g_erow[e]);
        float m0 = __ldcs(&g_ena[e]);
        float w0 = __ldcs(&g_ews[e]);
        const float* s0 = g_gath + (size_t)r0 * 256;
        accA += m0 * s0[tid];
        accS += w0 * s0[128 + tid];
    }
    accA *= g_dis[node];

    const float* ep = g_epi + (size_t)node * 256;
    float epA = __ldcs(&ep[tid]);
    float epS = __ldcs(&ep[128 + tid]);
    // ARMA: relu (leaky_relu+elu collapse on non-negative input)
    float v = accA + epA + arma_b[tid];
    __stcs(&out[(size_t)node * 256 + tid], fmaxf(v, 0.f));
    // SAGE: mean + lin + root, then leaky_relu -> elu
    float sage = accS / fmaxf((float)cnt, 1.f) + sage_lb[tid] + epS;
    __stcs(&out[(size_t)node * 256 + 128 + tid],
           (sage >= 0.f) ? sage : expm1f(0.01f * sage));
}

// ---------------- host launcher ----------------
extern "C" void kernel_launch(void* const* d_in, const int* in_sizes, int n_in,
                              void* d_out, int out_size) {
    const float* x       = (const float*)d_in[0];
    const void*  ei      = d_in[1];                 // int32 or int64, detected on device
    const float* ew      = (const float*)d_in[2];
    const float* W_pre   = (const float*)d_in[3];
    const float* b_pre   = (const float*)d_in[4];
    const float* w_ai    = (const float*)d_in[5];
    const float* w_ar    = (const float*)d_in[6];
    const float* arma_b  = (const float*)d_in[7];
    const float* w_sl    = (const float*)d_in[8];
    const float* sage_lb = (const float*)d_in[9];
    const float* w_sr    = (const float*)d_in[10];
    float* out = (float*)d_out;

    cudaFuncSetAttribute(gemm_kernel, cudaFuncAttributeMaxDynamicSharedMemorySize,
                         GEMM_SMEM);

    detect_kernel<<<1, 256>>>((const int*)ei);
    zero_kernel<<<(N_NODES + 255) / 256, 256>>>();
    hist_kernel<<<(N_EDGES + 255) / 256, 256>>>(ei, ew);
    scan1_kernel<<<NCHUNK, 128>>>();
    scan2_kernel<<<1, 1024>>>();
    scan3_kernel<<<NCHUNK, 128>>>();
    dis_kernel<<<(N_NODES + 255) / 256, 256>>>();
    fill_kernel<<<(N_EDGES + 255) / 256, 256>>>(ei, ew);

    fuse_w_kernel<<<129, 512>>>(W_pre, b_pre, w_ai, w_ar, w_sl, w_sr);
    dim3 ggrid((N_NODES + 127) / 128, 8);
    gemm_kernel<<<ggrid, 256, GEMM_SMEM>>>(x);

    agg_kernel<<<N_NODES, 128>>>(arma_b, sage_lb, out);
}

// round 13
// speedup vs baseline: 2.1008x; 1.1693x over previous
#include <cuda_runtime.h>
#include <cuda_bf16.h>
#include <cuda_fp16.h>
#include <math.h>

#define N_NODES 100000
#define N_EDGES 1600000
#define HID 128
#define OUT_D 128
#define NCHUNK ((N_NODES + 127) / 128)   // 782 scan chunks

// ---------------- device scratch (no allocations allowed) ----------------
// g_gath_h: per-node [t(128)|sl(128)] stored as 128 half2 (fp16) -> 512 B/node
__device__ __half2 g_gath_h[(size_t)N_NODES * 128];
__device__ float g_epi [(size_t)N_NODES * 256];   // per-node [r(128)|sr(128)] fp32
__device__ __nv_bfloat16 g_Wh[128 * 512];  // hi part of fused weights
__device__ __nv_bfloat16 g_Wl[128 * 512];  // lo part of fused weights
__device__ float g_bf[512];                // fused bias contribution of b_pre
__device__ float g_deg[N_NODES];           // weighted in-degree
__device__ int   g_cnti[N_NODES];          // integer in-degree
__device__ int   g_cursor[N_NODES];        // fill cursors
__device__ int   g_start[N_NODES];         // CSR start offsets
__device__ int   g_part[NCHUNK];           // scan partials
__device__ int   g_partoff[NCHUNK];        // scanned partials
__device__ float g_dis[N_NODES];
__device__ int   g_erow[N_EDGES];          // CSR: source node per slot
__device__ float g_ena[N_EDGES];           // CSR: dis[row]*w per slot
__device__ float g_ews[N_EDGES];           // CSR: w per slot
__device__ int   g_is64;                   // 1 if edge_index is int64 on device

// ---------------- index fetch helper (dtype-robust) ----------------
__device__ __forceinline__ long long fetch_idx(const void* EI, int is64, size_t pos) {
    if (is64) return ((const long long*)EI)[pos];
    return (long long)((const int*)EI)[pos];
}

// ---------------- tensor-core helpers ----------------
__device__ __forceinline__ void ldsm_x4(unsigned& r0, unsigned& r1, unsigned& r2, unsigned& r3,
                                        unsigned addr) {
    asm volatile("ldmatrix.sync.aligned.m8n8.x4.shared.b16 {%0,%1,%2,%3}, [%4];"
                 : "=r"(r0), "=r"(r1), "=r"(r2), "=r"(r3) : "r"(addr));
}
__device__ __forceinline__ void ldsm_x4_t(unsigned& r0, unsigned& r1, unsigned& r2, unsigned& r3,
                                          unsigned addr) {
    asm volatile("ldmatrix.sync.aligned.m8n8.x4.trans.shared.b16 {%0,%1,%2,%3}, [%4];"
                 : "=r"(r0), "=r"(r1), "=r"(r2), "=r"(r3) : "r"(addr));
}
__device__ __forceinline__ void mma_bf16(float* c, const unsigned* a, unsigned b0, unsigned b1) {
    asm volatile("mma.sync.aligned.m16n8k16.row.col.f32.bf16.bf16.f32 "
                 "{%0,%1,%2,%3}, {%4,%5,%6,%7}, {%8,%9}, {%0,%1,%2,%3};"
                 : "+f"(c[0]), "+f"(c[1]), "+f"(c[2]), "+f"(c[3])
                 : "r"(a[0]), "r"(a[1]), "r"(a[2]), "r"(a[3]), "r"(b0), "r"(b1));
}

// ---------------- detect index dtype ----------------
__global__ void detect_kernel(const int* __restrict__ EI32) {
    __shared__ int bad;
    if (threadIdx.x == 0) bad = 0;
    __syncthreads();
    int hi = EI32[2 * threadIdx.x + 1];   // high word of int64 #threadIdx.x
    if (hi != 0) atomicOr(&bad, 1);
    __syncthreads();
    if (threadIdx.x == 0) g_is64 = (bad == 0) ? 1 : 0;
}

// ---------------- zero small per-node scratch ----------------
__global__ void zero_kernel() {
    int i = blockIdx.x * blockDim.x + threadIdx.x;
    if (i >= N_NODES) return;
    g_deg[i] = 0.f;
    g_cnti[i] = 0;
    g_cursor[i] = 0;
}

// ---------------- histogram: weighted degree + count ----------------
__global__ void hist_kernel(const void* __restrict__ EI,
                            const float* __restrict__ EW) {
    int e = blockIdx.x * blockDim.x + threadIdx.x;
    if (e >= N_EDGES) return;
    long long col = fetch_idx(EI, g_is64, (size_t)N_EDGES + e);
    if ((unsigned long long)col >= N_NODES) return;  // safety
    atomicAdd(&g_deg[col], EW[e]);
    atomicAdd(&g_cnti[col], 1);
}

// ---------------- 2-level exclusive scan of g_cnti -> g_start ----------------
__global__ void scan1_kernel() {       // grid NCHUNK, block 128
    __shared__ int sd[128];
    int i = blockIdx.x * 128 + threadIdx.x;
    int v = (i < N_NODES) ? g_cnti[i] : 0;
    sd[threadIdx.x] = v;
    __syncthreads();
    #pragma unroll
    for (int off = 1; off < 128; off <<= 1) {
        int t = (threadIdx.x >= off) ? sd[threadIdx.x - off] : 0;
        __syncthreads();
        sd[threadIdx.x] += t;
        __syncthreads();
    }
    if (i < N_NODES) g_start[i] = sd[threadIdx.x] - v;   // exclusive
    if (threadIdx.x == 127) g_part[blockIdx.x] = sd[127];
}
__global__ void scan2_kernel() {       // 1 block, 1024 threads
    __shared__ int sd[1024];
    int v = (threadIdx.x < NCHUNK) ? g_part[threadIdx.x] : 0;
    sd[threadIdx.x] = v;
    __syncthreads();
    #pragma unroll
    for (int off = 1; off < 1024; off <<= 1) {
        int t = (threadIdx.x >= off) ? sd[threadIdx.x - off] : 0;
        __syncthreads();
        sd[threadIdx.x] += t;
        __syncthreads();
    }
    if (threadIdx.x < NCHUNK) g_partoff[threadIdx.x] = sd[threadIdx.x] - v;
}
__global__ void scan3_kernel() {       // grid NCHUNK, block 128
    int i = blockIdx.x * 128 + threadIdx.x;
    if (i < N_NODES) g_start[i] += g_partoff[blockIdx.x];
}

// ---------------- dis = deg > 0 ? rsqrt(max(deg,1e-12)) : 0 ----------------
__global__ void dis_kernel() {
    int i = blockIdx.x * blockDim.x + threadIdx.x;
    if (i >= N_NODES) return;
    float d = g_deg[i];
    g_dis[i] = (d > 0.f) ? rsqrtf(fmaxf(d, 1e-12f)) : 0.f;
}

// ---------------- fill CSR slots ----------------
__global__ void fill_kernel(const void* __restrict__ EI,
                            const float* __restrict__ EW) {
    int e = blockIdx.x * blockDim.x + threadIdx.x;
    if (e >= N_EDGES) return;
    int is64 = g_is64;
    long long row = fetch_idx(EI, is64, (size_t)e);
    long long col = fetch_idx(EI, is64, (size_t)N_EDGES + e);
    if ((unsigned long long)row >= N_NODES) return;  // safety
    if ((unsigned long long)col >= N_NODES) return;
    float w = EW[e];
    int pos = g_start[col] + atomicAdd(&g_cursor[col], 1);
    g_erow[pos] = (int)row;
    g_ena[pos]  = g_dis[row] * w;   // per-node dis[col] applied at aggregate
    g_ews[pos]  = w;
}

// ---------------- fuse weights + bias, emit bf16 hi/lo split ----------------
__global__ void fuse_w_kernel(const float* __restrict__ Wpre,
                              const float* __restrict__ bpre,
                              const float* __restrict__ w_ai,
                              const float* __restrict__ w_ar,
                              const float* __restrict__ w_sl,
                              const float* __restrict__ w_sr) {
    int c = blockIdx.x;      // 0..128
    int j = threadIdx.x;     // 0..511
    __shared__ float wrow[128];
    if (j < 128) wrow[j] = (c < 128) ? Wpre[c * 128 + j] : bpre[j];
    __syncthreads();
    const float* W2; int jj;
    if (j < 128)      { W2 = w_ai; jj = j;       }
    else if (j < 256) { W2 = w_ar; jj = j - 128; }
    else if (j < 384) { W2 = w_sl; jj = j - 256; }
    else              { W2 = w_sr; jj = j - 384; }
    float acc = 0.f;
    #pragma unroll 8
    for (int k = 0; k < 128; k++) acc += wrow[k] * W2[k * 128 + jj];
    if (c < 128) {
        __nv_bfloat16 hi = __float2bfloat16(acc);
        float lo = acc - __bfloat162float(hi);
        g_Wh[c * 512 + j] = hi;
        g_Wl[c * 512 + j] = __float2bfloat16(lo);
    } else {
        g_bf[j] = acc;
    }
}

// ---------------- tensor-core GEMM  Y[N,512] = X @ Wf + bf ----------------
// BM=128, BN=64 (blockIdx.y = 64-col slice of 512), K=128 resident.
// Quarters t/sl (wq 0,2) -> g_gath_h as fp16; quarters r/sr (wq 1,3) -> g_epi fp32.
#define PITCH 136    // A bf16 pitch (272B rows)
#define BPITCH 72    // B bf16 pitch (144B rows)
#define ATILE_B (128 * PITCH * 2)    // 34816 B
#define BTILE_B (128 * BPITCH * 2)   // 18432 B
#define GEMM_SMEM (2 * ATILE_B + 2 * BTILE_B)   // 106496 B
__global__ void __launch_bounds__(256, 2) gemm_kernel(const float* __restrict__ X) {
    extern __shared__ __align__(16) char sm[];
    __nv_bfloat16* As_hi = (__nv_bfloat16*)sm;
    __nv_bfloat16* As_lo = (__nv_bfloat16*)(sm + ATILE_B);
    __nv_bfloat16* Bs_hi = (__nv_bfloat16*)(sm + 2 * ATILE_B);
    __nv_bfloat16* Bs_lo = (__nv_bfloat16*)(sm + 2 * ATILE_B + BTILE_B);

    const int tid = threadIdx.x;
    const int m0 = blockIdx.x * 128;
    const int n0 = blockIdx.y * 64;       // within 512

    #pragma unroll
    for (int i = 0; i < 16; i++) {
        int f = tid + i * 256;            // 0..4095
        int r = f >> 5;                   // row 0..127
        int c4 = (f & 31) << 2;           // col 0,4,...,124
        float4 v = make_float4(0.f, 0.f, 0.f, 0.f);
        if (m0 + r < N_NODES)
            v = *(const float4*)&X[(size_t)(m0 + r) * 128 + c4];
        __nv_bfloat162 h01 = __floats2bfloat162_rn(v.x, v.y);
        __nv_bfloat162 h23 = __floats2bfloat162_rn(v.z, v.w);
        __nv_bfloat162 l01 = __floats2bfloat162_rn(v.x - __bfloat162float(h01.x),
                                                   v.y - __bfloat162float(h01.y));
        __nv_bfloat162 l23 = __floats2bfloat162_rn(v.z - __bfloat162float(h23.x),
                                                   v.w - __bfloat162float(h23.y));
        unsigned* ph = (unsigned*)&As_hi[r * PITCH + c4];
        unsigned* pl = (unsigned*)&As_lo[r * PITCH + c4];
        ph[0] = *(unsigned*)&h01; ph[1] = *(unsigned*)&h23;
        pl[0] = *(unsigned*)&l01; pl[1] = *(unsigned*)&l23;
    }
    #pragma unroll
    for (int i = 0; i < 8; i++) {
        int f = tid + i * 256;            // 0..2047 (uint2 = 4 bf16)
        int r = f >> 4;                   // row 0..127 (16 uint2 per row)
        int c4 = (f & 15) << 2;           // col 0,4,...,60
        uint2 vh = *(const uint2*)&g_Wh[r * 512 + n0 + c4];
        uint2 vl = *(const uint2*)&g_Wl[r * 512 + n0 + c4];
        *(uint2*)&Bs_hi[r * BPITCH + c4] = vh;
        *(uint2*)&Bs_lo[r * BPITCH + c4] = vl;
    }
    __syncthreads();

    const int lane = tid & 31;
    const int wid = tid >> 5;
    const int warp_m = wid & 3;   // 4 warps along m: 32 rows each
    const int warp_n = wid >> 2;  // 2 warps along n: 32 cols each

    float C[2][4][4];
    #pragma unroll
    for (int a = 0; a < 2; a++)
        #pragma unroll
        for (int b = 0; b < 4; b++)
            #pragma unroll
            for (int d = 0; d < 4; d++) C[a][b][d] = 0.f;

    const unsigned sa_hi = (unsigned)__cvta_generic_to_shared(As_hi);
    const unsigned sa_lo = (unsigned)__cvta_generic_to_shared(As_lo);
    const unsigned sb_hi = (unsigned)__cvta_generic_to_shared(Bs_hi);
    const unsigned sb_lo = (unsigned)__cvta_generic_to_shared(Bs_lo);
    const int lr = lane & 15;       // row-within-16
    const int lc = (lane >> 4) * 8; // col-half select

    #pragma unroll
    for (int ks = 0; ks < 8; ks++) {
        const int k0 = ks * 16;
        unsigned ah[2][4], al[2][4];
        #pragma unroll
        for (int mi = 0; mi < 2; mi++) {
            unsigned off = ((warp_m * 32 + mi * 16 + lr) * PITCH + k0 + lc) * 2;
            ldsm_x4(ah[mi][0], ah[mi][1], ah[mi][2], ah[mi][3], sa_hi + off);
            ldsm_x4(al[mi][0], al[mi][1], al[mi][2], al[mi][3], sa_lo + off);
        }
        unsigned bh[8], bl[8];
        #pragma unroll
        for (int nj = 0; nj < 2; nj++) {
            unsigned off = ((k0 + lr) * BPITCH + warp_n * 32 + nj * 16 + lc) * 2;
            ldsm_x4_t(bh[nj*4], bh[nj*4+1], bh[nj*4+2], bh[nj*4+3], sb_hi + off);
            ldsm_x4_t(bl[nj*4], bl[nj*4+1], bl[nj*4+2], bl[nj*4+3], sb_lo + off);
        }
        #pragma unroll
        for (int mi = 0; mi < 2; mi++)
            #pragma unroll
            for (int nf = 0; nf < 4; nf++) {
                int bi = (nf >> 1) * 4 + (nf & 1) * 2;
                mma_bf16(C[mi][nf], ah[mi], bh[bi], bh[bi + 1]);  // hi*hi
                mma_bf16(C[mi][nf], ah[mi], bl[bi], bl[bi + 1]);  // hi*lo
                mma_bf16(C[mi][nf], al[mi], bh[bi], bh[bi + 1]);  // lo*hi
            }
    }

    // ---- epilogue: bias + route quarter -> destination array/half ----
    const int wq = blockIdx.y >> 1;                  // 0=t,1=r,2=sl,3=sr
    const int half = blockIdx.y & 1;                 // which 64-col half of quarter
    const bool to_epi = (wq == 1 || wq == 3);
    // fp16 dest: half2 index within node row = sect*64 + half*32 + ncol/2
    const int h2base = ((wq == 2) ? 64 : 0) + half * 32;
    // fp32 dest (epi): col = sect*128 + half*64 + ncol
    const int colbase = ((wq == 3) ? 128 : 0) + half * 64;

    #pragma unroll
    for (int mi = 0; mi < 2; mi++) {
        #pragma unroll
        for (int nf = 0; nf < 4; nf++) {
            int ncol = warp_n * 32 + nf * 8 + (lane & 3) * 2;   // within 64, even
            float b0 = g_bf[n0 + ncol];
            float b1 = g_bf[n0 + ncol + 1];
            int r0 = m0 + warp_m * 32 + mi * 16 + (lane >> 2);
            int r1 = r0 + 8;
            if (to_epi) {
                if (r0 < N_NODES)
                    __stcs((float2*)&g_epi[(size_t)r0 * 256 + colbase + ncol],
                           make_float2(C[mi][nf][0] + b0, C[mi][nf][1] + b1));
                if (r1 < N_NODES)
                    __stcs((float2*)&g_epi[(size_t)r1 * 256 + colbase + ncol],
                           make_float2(C[mi][nf][2] + b0, C[mi][nf][3] + b1));
            } else {
                if (r0 < N_NODES)
                    g_gath_h[(size_t)r0 * 128 + h2base + (ncol >> 1)] =
                        __floats2half2_rn(C[mi][nf][0] + b0, C[mi][nf][1] + b1);
                if (r1 < N_NODES)
                    g_gath_h[(size_t)r1 * 128 + h2base + (ncol >> 1)] =
                        __floats2half2_rn(C[mi][nf][2] + b0, C[mi][nf][3] + b1);
            }
        }
    }
}

// ---------------- fused CSR aggregate + epilogue (no atomics, fp16 gather) ----
// One 128-thread block per node. Warps 0-1: ARMA half (t), warps 2-3: SAGE (sl).
// Each thread owns one half2 (2 feature columns); fp32 accumulation.
__global__ void __launch_bounds__(128) agg_kernel(const float* __restrict__ arma_b,
                                                  const float* __restrict__ sage_lb,
                                                  float* __restrict__ out) {
    const int node = blockIdx.x;
    const int tid = threadIdx.x;         // 0..127
    const bool isA = tid < 64;           // warp-uniform
    const int off = tid;                 // half2 index in node row (t: 0..63, sl: 64..127)

    const int s = g_start[node];
    const int cnt = g_cnti[node];
    const int e_end = s + cnt;

    float ax = 0.f, ay = 0.f;
    int e = s;
    for (; e + 2 <= e_end; e += 2) {
        int   r0 = __ldcs(&g_erow[e]);
        int   r1 = __ldcs(&g_erow[e + 1]);
        float m0 = isA ? __ldcs(&g_ena[e])     : __ldcs(&g_ews[e]);
        float m1 = isA ? __ldcs(&g_ena[e + 1]) : __ldcs(&g_ews[e + 1]);
        float2 f0 = __half22float2(g_gath_h[(size_t)r0 * 128 + off]);
        float2 f1 = __half22float2(g_gath_h[(size_t)r1 * 128 + off]);
        ax += m0 * f0.x + m1 * f1.x;
        ay += m0 * f0.y + m1 * f1.y;
    }
    if (e < e_end) {
        int   r0 = __ldcs(&g_erow[e]);
        float m0 = isA ? __ldcs(&g_ena[e]) : __ldcs(&g_ews[e]);
        float2 f0 = __half22float2(g_gath_h[(size_t)r0 * 128 + off]);
        ax += m0 * f0.x;
        ay += m0 * f0.y;
    }

    if (isA) {
        float dn = g_dis[node];
        ax *= dn; ay *= dn;
        int c0 = tid * 2;                           // ARMA cols c0, c0+1
        const float* ep = g_epi + (size_t)node * 256;
        float v0 = ax + __ldcs(&ep[c0])     + arma_b[c0];
        float v1 = ay + __ldcs(&ep[c0 + 1]) + arma_b[c0 + 1];
        // relu (leaky_relu+elu collapse on non-negative input)
        __stcs((float2*)&out[(size_t)node * 256 + c0],
               make_float2(fmaxf(v0, 0.f), fmaxf(v1, 0.f)));
    } else {
        float inv = 1.f / fmaxf((float)cnt, 1.f);
        int c0 = (tid - 64) * 2;                    // SAGE cols c0, c0+1
        const float* ep = g_epi + (size_t)node * 256 + 128;
        float s0 = ax * inv + sage_lb[c0]     + __ldcs(&ep[c0]);
        float s1 = ay * inv + sage_lb[c0 + 1] + __ldcs(&ep[c0 + 1]);
        // leaky_relu then elu: >=0 -> identity; <0 -> expm1(0.01*x)
        float o0 = (s0 >= 0.f) ? s0 : expm1f(0.01f * s0);
        float o1 = (s1 >= 0.f) ? s1 : expm1f(0.01f * s1);
        __stcs((float2*)&out[(size_t)node * 256 + 128 + c0], make_float2(o0, o1));
    }
}

// ---------------- host launcher ----------------
extern "C" void kernel_launch(void* const* d_in, const int* in_sizes, int n_in,
                              void* d_out, int out_size) {
    const float* x       = (const float*)d_in[0];
    const void*  ei      = d_in[1];                 // int32 or int64, detected on device
    const float* ew      = (const float*)d_in[2];
    const float* W_pre   = (const float*)d_in[3];
    const float* b_pre   = (const float*)d_in[4];
    const float* w_ai    = (const float*)d_in[5];
    const float* w_ar    = (const float*)d_in[6];
    const float* arma_b  = (const float*)d_in[7];
    const float* w_sl    = (const float*)d_in[8];
    const float* sage_lb = (const float*)d_in[9];
    const float* w_sr    = (const float*)d_in[10];
    float* out = (float*)d_out;

    cudaFuncSetAttribute(gemm_kernel, cudaFuncAttributeMaxDynamicSharedMemorySize,
                         GEMM_SMEM);

    detect_kernel<<<1, 256>>>((const int*)ei);
    zero_kernel<<<(N_NODES + 255) / 256, 256>>>();
    hist_kernel<<<(N_EDGES + 255) / 256, 256>>>(ei, ew);
    scan1_kernel<<<NCHUNK, 128>>>();
    scan2_kernel<<<1, 1024>>>();
    scan3_kernel<<<NCHUNK, 128>>>();
    dis_kernel<<<(N_NODES + 255) / 256, 256>>>();
    fill_kernel<<<(N_EDGES + 255) / 256, 256>>>(ei, ew);

    fuse_w_kernel<<<129, 512>>>(W_pre, b_pre, w_ai, w_ar, w_sl, w_sr);
    dim3 ggrid((N_NODES + 127) / 128, 8);
    gemm_kernel<<<ggrid, 256, GEMM_SMEM>>>(x);

    agg_kernel<<<N_NODES, 128>>>(arma_b, sage_lb, out);
}

// round 16
// speedup vs baseline: 2.3481x; 1.1177x over previous
#include <cuda_runtime.h>
#include <cuda_bf16.h>
#include <cuda_fp16.h>
#include <math.h>

#define N_NODES 100000
#define N_EDGES 1600000
#define HID 128
#define OUT_D 128
#define NCHUNK ((N_NODES + 127) / 128)   // 782 scan chunks

// ---------------- device scratch (no allocations allowed) ----------------
// g_gath_h: per-node [t(128)|sl(128)] stored as 128 half2 (fp16) -> 512 B/node
__device__ __half2 g_gath_h[(size_t)N_NODES * 128];
__device__ float g_epi [(size_t)N_NODES * 256];   // per-node [r(128)|sr(128)] fp32
__device__ __nv_bfloat16 g_Wh[128 * 512];  // hi part of fused weights
__device__ __nv_bfloat16 g_Wl[128 * 512];  // lo part of fused weights
__device__ float g_bf[512];                // fused bias contribution of b_pre
__device__ float g_deg[N_NODES];           // weighted in-degree
__device__ int   g_cnti[N_NODES];          // integer in-degree
__device__ int   g_cursor[N_NODES];        // fill cursors
__device__ int   g_start[N_NODES];         // CSR start offsets
__device__ int   g_part[NCHUNK];           // scan partials
__device__ int   g_partoff[NCHUNK];        // scanned partials
__device__ float g_dis[N_NODES];
__device__ int   g_erow[N_EDGES];          // CSR: source node per slot
__device__ float g_ena[N_EDGES];           // CSR: dis[row]*w per slot
__device__ float g_ews[N_EDGES];           // CSR: w per slot
__device__ int   g_is64;                   // 1 if edge_index is int64 on device

// ---------------- index fetch helper (dtype-robust) ----------------
__device__ __forceinline__ long long fetch_idx(const void* EI, int is64, size_t pos) {
    if (is64) return ((const long long*)EI)[pos];
    return (long long)((const int*)EI)[pos];
}

// ---------------- tensor-core helpers ----------------
__device__ __forceinline__ void ldsm_x4(unsigned& r0, unsigned& r1, unsigned& r2, unsigned& r3,
                                        unsigned addr) {
    asm volatile("ldmatrix.sync.aligned.m8n8.x4.shared.b16 {%0,%1,%2,%3}, [%4];"
                 : "=r"(r0), "=r"(r1), "=r"(r2), "=r"(r3) : "r"(addr));
}
__device__ __forceinline__ void ldsm_x4_t(unsigned& r0, unsigned& r1, unsigned& r2, unsigned& r3,
                                          unsigned addr) {
    asm volatile("ldmatrix.sync.aligned.m8n8.x4.trans.shared.b16 {%0,%1,%2,%3}, [%4];"
                 : "=r"(r0), "=r"(r1), "=r"(r2), "=r"(r3) : "r"(addr));
}
__device__ __forceinline__ void mma_bf16(float* c, const unsigned* a, unsigned b0, unsigned b1) {
    asm volatile("mma.sync.aligned.m16n8k16.row.col.f32.bf16.bf16.f32 "
                 "{%0,%1,%2,%3}, {%4,%5,%6,%7}, {%8,%9}, {%0,%1,%2,%3};"
                 : "+f"(c[0]), "+f"(c[1]), "+f"(c[2]), "+f"(c[3])
                 : "r"(a[0]), "r"(a[1]), "r"(a[2]), "r"(a[3]), "r"(b0), "r"(b1));
}

// ---------------- detect index dtype ----------------
__global__ void detect_kernel(const int* __restrict__ EI32) {
    __shared__ int bad;
    if (threadIdx.x == 0) bad = 0;
    __syncthreads();
    int hi = EI32[2 * threadIdx.x + 1];   // high word of int64 #threadIdx.x
    if (hi != 0) atomicOr(&bad, 1);
    __syncthreads();
    if (threadIdx.x == 0) g_is64 = (bad == 0) ? 1 : 0;
}

// ---------------- zero small per-node scratch ----------------
__global__ void zero_kernel() {
    int i = blockIdx.x * blockDim.x + threadIdx.x;
    if (i >= N_NODES) return;
    g_deg[i] = 0.f;
    g_cnti[i] = 0;
    g_cursor[i] = 0;
}

// ---------------- histogram: weighted degree + count ----------------
__global__ void hist_kernel(const void* __restrict__ EI,
                            const float* __restrict__ EW) {
    int e = blockIdx.x * blockDim.x + threadIdx.x;
    if (e >= N_EDGES) return;
    long long col = fetch_idx(EI, g_is64, (size_t)N_EDGES + e);
    if ((unsigned long long)col >= N_NODES) return;  // safety
    atomicAdd(&g_deg[col], EW[e]);
    atomicAdd(&g_cnti[col], 1);
}

// ---------------- 2-level exclusive scan of g_cnti -> g_start ----------------
__global__ void scan1_kernel() {       // grid NCHUNK, block 128
    __shared__ int sd[128];
    int i = blockIdx.x * 128 + threadIdx.x;
    int v = (i < N_NODES) ? g_cnti[i] : 0;
    sd[threadIdx.x] = v;
    __syncthreads();
    #pragma unroll
    for (int off = 1; off < 128; off <<= 1) {
        int t = (threadIdx.x >= off) ? sd[threadIdx.x - off] : 0;
        __syncthreads();
        sd[threadIdx.x] += t;
        __syncthreads();
    }
    if (i < N_NODES) g_start[i] = sd[threadIdx.x] - v;   // exclusive
    if (threadIdx.x == 127) g_part[blockIdx.x] = sd[127];
}
__global__ void scan2_kernel() {       // 1 block, 1024 threads
    __shared__ int sd[1024];
    int v = (threadIdx.x < NCHUNK) ? g_part[threadIdx.x] : 0;
    sd[threadIdx.x] = v;
    __syncthreads();
    #pragma unroll
    for (int off = 1; off < 1024; off <<= 1) {
        int t = (threadIdx.x >= off) ? sd[threadIdx.x - off] : 0;
        __syncthreads();
        sd[threadIdx.x] += t;
        __syncthreads();
    }
    if (threadIdx.x < NCHUNK) g_partoff[threadIdx.x] = sd[threadIdx.x] - v;
}
__global__ void scan3_kernel() {       // grid NCHUNK, block 128
    int i = blockIdx.x * 128 + threadIdx.x;
    if (i < N_NODES) g_start[i] += g_partoff[blockIdx.x];
}

// ---------------- dis = deg > 0 ? rsqrt(max(deg,1e-12)) : 0 ----------------
__global__ void dis_kernel() {
    int i = blockIdx.x * blockDim.x + threadIdx.x;
    if (i >= N_NODES) return;
    float d = g_deg[i];
    g_dis[i] = (d > 0.f) ? rsqrtf(fmaxf(d, 1e-12f)) : 0.f;
}

// ---------------- fill CSR slots ----------------
__global__ void fill_kernel(const void* __restrict__ EI,
                            const float* __restrict__ EW) {
    int e = blockIdx.x * blockDim.x + threadIdx.x;
    if (e >= N_EDGES) return;
    int is64 = g_is64;
    long long row = fetch_idx(EI, is64, (size_t)e);
    long long col = fetch_idx(EI, is64, (size_t)N_EDGES + e);
    if ((unsigned long long)row >= N_NODES) return;  // safety
    if ((unsigned long long)col >= N_NODES) return;
    float w = EW[e];
    int pos = g_start[col] + atomicAdd(&g_cursor[col], 1);
    g_erow[pos] = (int)row;
    g_ena[pos]  = g_dis[row] * w;   // per-node dis[col] applied at aggregate
    g_ews[pos]  = w;
}

// ---------------- fuse weights + bias, emit bf16 hi/lo split ----------------
__global__ void fuse_w_kernel(const float* __restrict__ Wpre,
                              const float* __restrict__ bpre,
                              const float* __restrict__ w_ai,
                              const float* __restrict__ w_ar,
                              const float* __restrict__ w_sl,
                              const float* __restrict__ w_sr) {
    int c = blockIdx.x;      // 0..128
    int j = threadIdx.x;     // 0..511
    __shared__ float wrow[128];
    if (j < 128) wrow[j] = (c < 128) ? Wpre[c * 128 + j] : bpre[j];
    __syncthreads();
    const float* W2; int jj;
    if (j < 128)      { W2 = w_ai; jj = j;       }
    else if (j < 256) { W2 = w_ar; jj = j - 128; }
    else if (j < 384) { W2 = w_sl; jj = j - 256; }
    else              { W2 = w_sr; jj = j - 384; }
    float acc = 0.f;
    #pragma unroll 8
    for (int k = 0; k < 128; k++) acc += wrow[k] * W2[k * 128 + jj];
    if (c < 128) {
        __nv_bfloat16 hi = __float2bfloat16(acc);
        float lo = acc - __bfloat162float(hi);
        g_Wh[c * 512 + j] = hi;
        g_Wl[c * 512 + j] = __float2bfloat16(lo);
    } else {
        g_bf[j] = acc;
    }
}

// ---------------- tensor-core GEMM  Y[N,512] = X @ Wf + bf ----------------
// BM=128; A loaded/converted ONCE per CTA; loop over 8 BN=64 weight slices
// (weights are L2-hot: 256 KB total). smem 106.5 KB -> 2 CTAs/SM.
#define PITCH 136    // A bf16 pitch (272B rows)
#define BPITCH 72    // B bf16 pitch (144B rows)
#define ATILE_B (128 * PITCH * 2)    // 34816 B
#define BTILE_B (128 * BPITCH * 2)   // 18432 B
#define GEMM_SMEM (2 * ATILE_B + 2 * BTILE_B)   // 106496 B
__global__ void __launch_bounds__(256, 2) gemm_kernel(const float* __restrict__ X) {
    extern __shared__ __align__(16) char sm[];
    __nv_bfloat16* As_hi = (__nv_bfloat16*)sm;
    __nv_bfloat16* As_lo = (__nv_bfloat16*)(sm + ATILE_B);
    __nv_bfloat16* Bs_hi = (__nv_bfloat16*)(sm + 2 * ATILE_B);
    __nv_bfloat16* Bs_lo = (__nv_bfloat16*)(sm + 2 * ATILE_B + BTILE_B);

    const int tid = threadIdx.x;
    const int m0 = blockIdx.x * 128;

    // ---- stage A once (fp32 -> hi/lo bf16), 16 float4 per thread ----
    #pragma unroll
    for (int i = 0; i < 16; i++) {
        int f = tid + i * 256;            // 0..4095
        int r = f >> 5;                   // row 0..127
        int c4 = (f & 31) << 2;           // col 0,4,...,124
        float4 v = make_float4(0.f, 0.f, 0.f, 0.f);
        if (m0 + r < N_NODES)
            v = *(const float4*)&X[(size_t)(m0 + r) * 128 + c4];
        __nv_bfloat162 h01 = __floats2bfloat162_rn(v.x, v.y);
        __nv_bfloat162 h23 = __floats2bfloat162_rn(v.z, v.w);
        __nv_bfloat162 l01 = __floats2bfloat162_rn(v.x - __bfloat162float(h01.x),
                                                   v.y - __bfloat162float(h01.y));
        __nv_bfloat162 l23 = __floats2bfloat162_rn(v.z - __bfloat162float(h23.x),
                                                   v.w - __bfloat162float(h23.y));
        unsigned* ph = (unsigned*)&As_hi[r * PITCH + c4];
        unsigned* pl = (unsigned*)&As_lo[r * PITCH + c4];
        ph[0] = *(unsigned*)&h01; ph[1] = *(unsigned*)&h23;
        pl[0] = *(unsigned*)&l01; pl[1] = *(unsigned*)&l23;
    }

    const int lane = tid & 31;
    const int wid = tid >> 5;
    const int warp_m = wid & 3;   // 4 warps along m: 32 rows each
    const int warp_n = wid >> 2;  // 2 warps along n: 32 cols each

    const unsigned sa_hi = (unsigned)__cvta_generic_to_shared(As_hi);
    const unsigned sa_lo = (unsigned)__cvta_generic_to_shared(As_lo);
    const unsigned sb_hi = (unsigned)__cvta_generic_to_shared(Bs_hi);
    const unsigned sb_lo = (unsigned)__cvta_generic_to_shared(Bs_lo);
    const int lr = lane & 15;       // row-within-16
    const int lc = (lane >> 4) * 8; // col-half select

    for (int ny = 0; ny < 8; ny++) {
        const int n0 = ny * 64;
        __syncthreads();   // previous slice's mma done before B overwrite
        // ---- stage B slice [128k][64n]: 8 uint2 per thread per tile ----
        #pragma unroll
        for (int i = 0; i < 8; i++) {
            int f = tid + i * 256;            // 0..2047 (uint2 = 4 bf16)
            int r = f >> 4;                   // row 0..127 (16 uint2 per row)
            int c4 = (f & 15) << 2;           // col 0,4,...,60
            uint2 vh = *(const uint2*)&g_Wh[r * 512 + n0 + c4];
            uint2 vl = *(const uint2*)&g_Wl[r * 512 + n0 + c4];
            *(uint2*)&Bs_hi[r * BPITCH + c4] = vh;
            *(uint2*)&Bs_lo[r * BPITCH + c4] = vl;
        }
        __syncthreads();

        float C[2][4][4];
        #pragma unroll
        for (int a = 0; a < 2; a++)
            #pragma unroll
            for (int b = 0; b < 4; b++)
                #pragma unroll
                for (int d = 0; d < 4; d++) C[a][b][d] = 0.f;

        #pragma unroll
        for (int ks = 0; ks < 8; ks++) {
            const int k0 = ks * 16;
            unsigned ah[2][4], al[2][4];
            #pragma unroll
            for (int mi = 0; mi < 2; mi++) {
                unsigned off = ((warp_m * 32 + mi * 16 + lr) * PITCH + k0 + lc) * 2;
                ldsm_x4(ah[mi][0], ah[mi][1], ah[mi][2], ah[mi][3], sa_hi + off);
                ldsm_x4(al[mi][0], al[mi][1], al[mi][2], al[mi][3], sa_lo + off);
            }
            unsigned bh[8], bl[8];
            #pragma unroll
            for (int nj = 0; nj < 2; nj++) {
                unsigned off = ((k0 + lr) * BPITCH + warp_n * 32 + nj * 16 + lc) * 2;
                ldsm_x4_t(bh[nj*4], bh[nj*4+1], bh[nj*4+2], bh[nj*4+3], sb_hi + off);
                ldsm_x4_t(bl[nj*4], bl[nj*4+1], bl[nj*4+2], bl[nj*4+3], sb_lo + off);
            }
            #pragma unroll
            for (int mi = 0; mi < 2; mi++)
                #pragma unroll
                for (int nf = 0; nf < 4; nf++) {
                    int bi = (nf >> 1) * 4 + (nf & 1) * 2;
                    mma_bf16(C[mi][nf], ah[mi], bh[bi], bh[bi + 1]);  // hi*hi
                    mma_bf16(C[mi][nf], ah[mi], bl[bi], bl[bi + 1]);  // hi*lo
                    mma_bf16(C[mi][nf], al[mi], bh[bi], bh[bi + 1]);  // lo*hi
                }
        }

        // ---- epilogue for this slice ----
        const int wq = ny >> 1;                  // 0=t,1=r,2=sl,3=sr
        const int half = ny & 1;                 // 64-col half of quarter
        const bool to_epi = (wq == 1 || wq == 3);
        const int h2base = ((wq == 2) ? 64 : 0) + half * 32;          // fp16 dest
        const int colbase = ((wq == 3) ? 128 : 0) + half * 64;        // fp32 dest

        #pragma unroll
        for (int mi = 0; mi < 2; mi++) {
            #pragma unroll
            for (int nf = 0; nf < 4; nf++) {
                int ncol = warp_n * 32 + nf * 8 + (lane & 3) * 2;   // within 64, even
                float b0 = g_bf[n0 + ncol];
                float b1 = g_bf[n0 + ncol + 1];
                int r0 = m0 + warp_m * 32 + mi * 16 + (lane >> 2);
                int r1 = r0 + 8;
                if (to_epi) {
                    if (r0 < N_NODES)
                        __stcs((float2*)&g_epi[(size_t)r0 * 256 + colbase + ncol],
                               make_float2(C[mi][nf][0] + b0, C[mi][nf][1] + b1));
                    if (r1 < N_NODES)
                        __stcs((float2*)&g_epi[(size_t)r1 * 256 + colbase + ncol],
                               make_float2(C[mi][nf][2] + b0, C[mi][nf][3] + b1));
                } else {
                    if (r0 < N_NODES)
                        g_gath_h[(size_t)r0 * 128 + h2base + (ncol >> 1)] =
                            __floats2half2_rn(C[mi][nf][0] + b0, C[mi][nf][1] + b1);
                    if (r1 < N_NODES)
                        g_gath_h[(size_t)r1 * 128 + h2base + (ncol >> 1)] =
                            __floats2half2_rn(C[mi][nf][2] + b0, C[mi][nf][3] + b1);
                }
            }
        }
    }
}

// ---------------- fused CSR aggregate + epilogue (no atomics, fp16 gather) ----
// One 128-thread block per node. Threads 0-63: ARMA half (t), 64-127: SAGE (sl).
// Unroll-by-4 for gather MLP; fp32 accumulation.
__global__ void __launch_bounds__(128) agg_kernel(const float* __restrict__ arma_b,
                                                  const float* __restrict__ sage_lb,
                                                  float* __restrict__ out) {
    const int node = blockIdx.x;
    const int tid = threadIdx.x;         // 0..127
    const bool isA = tid < 64;           // warp-uniform
    const int off = tid;                 // half2 index in node row

    const int s = g_start[node];
    const int cnt = g_cnti[node];
    const int e_end = s + cnt;

    float ax = 0.f, ay = 0.f;
    int e = s;
    for (; e + 4 <= e_end; e += 4) {
        int r0 = __ldcs(&g_erow[e]);
        int r1 = __ldcs(&g_erow[e + 1]);
        int r2 = __ldcs(&g_erow[e + 2]);
        int r3 = __ldcs(&g_erow[e + 3]);
        float m0 = isA ? __ldcs(&g_ena[e])     : __ldcs(&g_ews[e]);
        float m1 = isA ? __ldcs(&g_ena[e + 1]) : __ldcs(&g_ews[e + 1]);
        float m2 = isA ? __ldcs(&g_ena[e + 2]) : __ldcs(&g_ews[e + 2]);
        float m3 = isA ? __ldcs(&g_ena[e + 3]) : __ldcs(&g_ews[e + 3]);
        float2 f0 = __half22float2(g_gath_h[(size_t)r0 * 128 + off]);
        float2 f1 = __half22float2(g_gath_h[(size_t)r1 * 128 + off]);
        float2 f2 = __half22float2(g_gath_h[(size_t)r2 * 128 + off]);
        float2 f3 = __half22float2(g_gath_h[(size_t)r3 * 128 + off]);
        ax += m0 * f0.x + m1 * f1.x + m2 * f2.x + m3 * f3.x;
        ay += m0 * f0.y + m1 * f1.y + m2 * f2.y + m3 * f3.y;
    }
    for (; e < e_end; e++) {
        int   r0 = __ldcs(&g_erow[e]);
        float m0 = isA ? __ldcs(&g_ena[e]) : __ldcs(&g_ews[e]);
        float2 f0 = __half22float2(g_gath_h[(size_t)r0 * 128 + off]);
        ax += m0 * f0.x;
        ay += m0 * f0.y;
    }

    if (isA) {
        float dn = g_dis[node];
        ax *= dn; ay *= dn;
        int c0 = tid * 2;                           // ARMA cols c0, c0+1
        const float* ep = g_epi + (size_t)node * 256;
        float v0 = ax + __ldcs(&ep[c0])     + arma_b[c0];
        float v1 = ay + __ldcs(&ep[c0 + 1]) + arma_b[c0 + 1];
        // relu (leaky_relu+elu collapse on non-negative input)
        __stcs((float2*)&out[(size_t)node * 256 + c0],
               make_float2(fmaxf(v0, 0.f), fmaxf(v1, 0.f)));
    } else {
        float inv = 1.f / fmaxf((float)cnt, 1.f);
        int c0 = (tid - 64) * 2;                    // SAGE cols c0, c0+1
        const float* ep = g_epi + (size_t)node * 256 + 128;
        float s0 = ax * inv + sage_lb[c0]     + __ldcs(&ep[c0]);
        float s1 = ay * inv + sage_lb[c0 + 1] + __ldcs(&ep[c0 + 1]);
        // leaky_relu then elu: >=0 -> identity; <0 -> expm1(0.01*x)
        float o0 = (s0 >= 0.f) ? s0 : expm1f(0.01f * s0);
        float o1 = (s1 >= 0.f) ? s1 : expm1f(0.01f * s1);
        __stcs((float2*)&out[(size_t)node * 256 + 128 + c0], make_float2(o0, o1));
    }
}

// ---------------- host launcher ----------------
extern "C" void kernel_launch(void* const* d_in, const int* in_sizes, int n_in,
                              void* d_out, int out_size) {
    const float* x       = (const float*)d_in[0];
    const void*  ei      = d_in[1];                 // int32 or int64, detected on device
    const float* ew      = (const float*)d_in[2];
    const float* W_pre   = (const float*)d_in[3];
    const float* b_pre   = (const float*)d_in[4];
    const float* w_ai    = (const float*)d_in[5];
    const float* w_ar    = (const float*)d_in[6];
    const float* arma_b  = (const float*)d_in[7];
    const float* w_sl    = (const float*)d_in[8];
    const float* sage_lb = (const float*)d_in[9];
    const float* w_sr    = (const float*)d_in[10];
    float* out = (float*)d_out;

    cudaFuncSetAttribute(gemm_kernel, cudaFuncAttributeMaxDynamicSharedMemorySize,
                         GEMM_SMEM);

    detect_kernel<<<1, 256>>>((const int*)ei);
    zero_kernel<<<(N_NODES + 255) / 256, 256>>>();
    hist_kernel<<<(N_EDGES + 255) / 256, 256>>>(ei, ew);
    scan1_kernel<<<NCHUNK, 128>>>();
    scan2_kernel<<<1, 1024>>>();
    scan3_kernel<<<NCHUNK, 128>>>();
    dis_kernel<<<(N_NODES + 255) / 256, 256>>>();
    fill_kernel<<<(N_EDGES + 255) / 256, 256>>>(ei, ew);

    fuse_w_kernel<<<129, 512>>>(W_pre, b_pre, w_ai, w_ar, w_sl, w_sr);
    gemm_kernel<<<(N_NODES + 127) / 128, 256, GEMM_SMEM>>>(x);

    agg_kernel<<<N_NODES, 128>>>(arma_b, sage_lb, out);
}